// round 1
// baseline (speedup 1.0000x reference)
#include <cuda_runtime.h>
#include <math.h>

#define T_SEQ 2048
#define NTOK  4096
#define DM    512
#define NH    8
#define DH    64
#define DP    32

// ---------------- scratch (device globals; no allocations allowed) ----------
__device__ float g_wqk[512 * 512];     // packed [n][k]: n<256 -> q head/out, else k
__device__ float g_qkraw[NTOK * 512];
__device__ float g_q[16 * T_SEQ * DP]; // [bh][t][o], gain & 1/sqrt(32) folded in
__device__ float g_k[16 * T_SEQ * DP];
__device__ float g_v[NTOK * DM];
__device__ float g_y[NTOK * DM];
__device__ float g_h[NTOK * DM];
__device__ float g_he0[NTOK * DM];
__device__ float g_ln[NTOK * DM];
__device__ float g_he1[NTOK * DM];
__device__ float g_he2[NTOK * DM];
__device__ float g_hrms[NTOK * DM];
__device__ float g_cos[T_SEQ * 16];
__device__ float g_sin[T_SEQ * 16];

// ---------------- RoPE trig table (double precision, fast-math-proof) -------
__global__ void trig_table_kernel() {
    int idx = blockIdx.x * blockDim.x + threadIdx.x;
    if (idx >= T_SEQ * 16) return;
    int t = idx >> 4, i = idx & 15;
    double p = pow(10000.0, (double)i / 16.0);
    float pf = (float)p;
    float freq = 1.0f / pf;                 // matches ref's fp32 1/10000**e
    float ang = (float)t * freq;            // matches ref's fp32 product
    g_cos[idx] = (float)cos((double)ang);
    g_sin[idx] = (float)sin((double)ang);
}

// ---------------- pack q_projs/k_projs [h][d][o] -> W[n][d] -----------------
__global__ void prep_wqk_kernel(const float* __restrict__ qp,
                                const float* __restrict__ kp) {
    int n = blockIdx.x;
    const float* src = (n < 256) ? qp : kp;
    int nn = n & 255;
    int h = nn >> 5, o = nn & 31;
    for (int d = threadIdx.x; d < 512; d += blockDim.x)
        g_wqk[n * 512 + d] = src[h * 16384 + d * 32 + o];
}

// ---------------- generic fp32 GEMM: C[m,n] = sum_k A[m,k]*W[n,k] -----------
// epi: 0 = none, 1 = C = R + acc, 2 = C = R + silu(acc)
__global__ __launch_bounds__(256) void gemm_nt_kernel(
    const float* __restrict__ A, const float* __restrict__ W,
    const float* __restrict__ R, float* __restrict__ C,
    int K, int N, int epi)
{
    __shared__ __align__(16) float As[16][64];
    __shared__ __align__(16) float Ws[16][64];
    int tid = threadIdx.x;
    int bm = blockIdx.y * 64, bn = blockIdx.x * 64;
    int lr = tid >> 2;
    int lc = (tid & 3) << 2;
    int tx = tid & 15, ty = tid >> 4;
    const float* Ap = A + (size_t)(bm + lr) * K + lc;
    const float* Wp = W + (size_t)(bn + lr) * K + lc;

    float acc[16];
#pragma unroll
    for (int i = 0; i < 16; i++) acc[i] = 0.f;

    for (int k0 = 0; k0 < K; k0 += 16) {
        float4 av = *(const float4*)(Ap + k0);
        float4 wv = *(const float4*)(Wp + k0);
        As[lc + 0][lr] = av.x; As[lc + 1][lr] = av.y;
        As[lc + 2][lr] = av.z; As[lc + 3][lr] = av.w;
        Ws[lc + 0][lr] = wv.x; Ws[lc + 1][lr] = wv.y;
        Ws[lc + 2][lr] = wv.z; Ws[lc + 3][lr] = wv.w;
        __syncthreads();
#pragma unroll
        for (int kk = 0; kk < 16; kk++) {
            float4 a = *(const float4*)&As[kk][ty * 4];
            float4 b = *(const float4*)&Ws[kk][tx * 4];
            acc[0]  += a.x * b.x; acc[1]  += a.x * b.y; acc[2]  += a.x * b.z; acc[3]  += a.x * b.w;
            acc[4]  += a.y * b.x; acc[5]  += a.y * b.y; acc[6]  += a.y * b.z; acc[7]  += a.y * b.w;
            acc[8]  += a.z * b.x; acc[9]  += a.z * b.y; acc[10] += a.z * b.z; acc[11] += a.z * b.w;
            acc[12] += a.w * b.x; acc[13] += a.w * b.y; acc[14] += a.w * b.z; acc[15] += a.w * b.w;
        }
        __syncthreads();
    }
#pragma unroll
    for (int i = 0; i < 4; i++) {
        int row = bm + ty * 4 + i;
#pragma unroll
        for (int j = 0; j < 4; j++) {
            int col = bn + tx * 4 + j;
            size_t idx = (size_t)row * N + col;
            float v = acc[i * 4 + j];
            if (epi == 1) {
                v = R[idx] + v;
            } else if (epi == 2) {
                float sg = 1.0f / (1.0f + expf(-v));
                v = R[idx] + v * sg;
            }
            C[idx] = v;
        }
    }
}

// ---------------- RoPE + gain + score-scale fold ----------------------------
__global__ __launch_bounds__(256) void rope_kernel(const float* __restrict__ qkraw,
                                                   const float* __restrict__ gain) {
    int token = blockIdx.x;
    int b = token >> 11, t = token & 2047;
    int tid = threadIdx.x;
    int h = tid >> 5, o = tid & 31, i = o & 15;
    float c = g_cos[t * 16 + i];
    float s = g_sin[t * 16 + i];
    const float* row = qkraw + (size_t)token * 512;
    size_t oidx = ((size_t)(b * 8 + h) * T_SEQ + t) * DP + o;

    float q1 = row[h * 32 + i], q2 = row[h * 32 + i + 16];
    float qv = (o < 16) ? (q1 * c - q2 * s) : (q2 * c + q1 * s);
    g_q[oidx] = qv * (gain[h] * 0.17677669529663687f); // 1/sqrt(32)

    float k1 = row[256 + h * 32 + i], k2 = row[256 + h * 32 + i + 16];
    g_k[oidx] = (o < 16) ? (k1 * c - k2 * s) : (k2 * c + k1 * s);
}

// ---------------- flash attention + self-align epilogue ---------------------
__global__ __launch_bounds__(128, 1) void attn_kernel() {
    __shared__ __align__(16) float ks[128 * 32];
    __shared__ __align__(16) float vs[128 * 64];
    int bh = blockIdx.y, b = bh >> 3, h = bh & 7;
    int tileIdx = (int)gridDim.x - 1 - (int)blockIdx.x; // heavy tiles first
    int tid = threadIdx.x;
    int r = tileIdx * 128 + tid;

    float q[32];
    {
        const float4* qr = (const float4*)(g_q + ((size_t)bh * T_SEQ + r) * DP);
#pragma unroll
        for (int i = 0; i < 8; i++) {
            float4 t4 = qr[i];
            q[4 * i] = t4.x; q[4 * i + 1] = t4.y; q[4 * i + 2] = t4.z; q[4 * i + 3] = t4.w;
        }
    }
    float acc[64];
#pragma unroll
    for (int d = 0; d < 64; d++) acc[d] = 0.f;
    float mrow = -3.0e38f, l = 0.f;

    int ntiles = tileIdx + 1;
    for (int tile = 0; tile < ntiles; tile++) {
        int j0 = tile * 128;
        {
            const float4* src = (const float4*)(g_k + ((size_t)bh * T_SEQ + j0) * DP);
            float4* dst = (float4*)ks;
#pragma unroll
            for (int i = 0; i < 8; i++) dst[tid + 128 * i] = src[tid + 128 * i];
            float4* vd = (float4*)vs;
#pragma unroll
            for (int i = 0; i < 16; i++) {
                int idx = tid + 128 * i;
                int row = idx >> 4, seg = idx & 15;
                vd[idx] = *(const float4*)(g_v + ((size_t)(b * T_SEQ + j0 + row)) * DM + h * DH + seg * 4);
            }
        }
        __syncthreads();

        for (int jc = 0; jc < 128; jc += 16) {
            float sc[16];
            float cmax = -3.0e38f;
#pragma unroll
            for (int jj = 0; jj < 16; jj++) {
                const float4* kr = (const float4*)(ks + (jc + jj) * 32);
                float s0 = 0, s1 = 0, s2 = 0, s3 = 0;
#pragma unroll
                for (int d4 = 0; d4 < 8; d4++) {
                    float4 kv = kr[d4];
                    s0 += q[4 * d4]     * kv.x;
                    s1 += q[4 * d4 + 1] * kv.y;
                    s2 += q[4 * d4 + 2] * kv.z;
                    s3 += q[4 * d4 + 3] * kv.w;
                }
                float s = (s0 + s1) + (s2 + s3);
                s = (j0 + jc + jj <= r) ? s : -3.0e38f;
                sc[jj] = s;
                cmax = fmaxf(cmax, s);
            }
            float mnew = fmaxf(mrow, cmax);
            float corr = __expf(mrow - mnew);
            float psum = 0.f;
#pragma unroll
            for (int jj = 0; jj < 16; jj++) { sc[jj] = __expf(sc[jj] - mnew); psum += sc[jj]; }
            l = l * corr + psum;
            mrow = mnew;
#pragma unroll
            for (int d = 0; d < 64; d++) acc[d] *= corr;
#pragma unroll
            for (int jj = 0; jj < 16; jj++) {
                float pj = sc[jj];
                const float4* vr = (const float4*)(vs + (jc + jj) * 64);
#pragma unroll
                for (int d4 = 0; d4 < 16; d4++) {
                    float4 vv = vr[d4];
                    acc[4 * d4]     += pj * vv.x;
                    acc[4 * d4 + 1] += pj * vv.y;
                    acc[4 * d4 + 2] += pj * vv.z;
                    acc[4 * d4 + 3] += pj * vv.w;
                }
            }
        }
        __syncthreads();
    }

    // y = acc/l ; self-align removal against v_norm of own position
    float invl = 1.f / l;
#pragma unroll
    for (int d = 0; d < 64; d++) acc[d] *= invl;
    const float* vrow = g_v + ((size_t)(b * T_SEQ + r)) * DM + h * DH;
    float n2 = 0.f;
#pragma unroll
    for (int d4 = 0; d4 < 16; d4++) {
        float4 vv = *(const float4*)(vrow + 4 * d4);
        n2 += vv.x * vv.x + vv.y * vv.y + vv.z * vv.z + vv.w * vv.w;
    }
    float rn = 1.f / fmaxf(sqrtf(n2), 1e-12f);
    float proj = 0.f;
#pragma unroll
    for (int d4 = 0; d4 < 16; d4++) {
        float4 vv = *(const float4*)(vrow + 4 * d4);
        proj += acc[4 * d4] * vv.x + acc[4 * d4 + 1] * vv.y
              + acc[4 * d4 + 2] * vv.z + acc[4 * d4 + 3] * vv.w;
    }
    proj *= rn;                 // = sum(y * v_norm)
    float prn = proj * rn;
    float* yrow = g_y + ((size_t)(b * T_SEQ + r)) * DM + h * DH;
#pragma unroll
    for (int d4 = 0; d4 < 16; d4++) {
        float4 vv = *(const float4*)(vrow + 4 * d4);
        float4 o;
        o.x = acc[4 * d4]     - prn * vv.x;
        o.y = acc[4 * d4 + 1] - prn * vv.y;
        o.z = acc[4 * d4 + 2] - prn * vv.z;
        o.w = acc[4 * d4 + 3] - prn * vv.w;
        *(float4*)(yrow + 4 * d4) = o;
    }
}

// ---------------- layernorm ------------------------------------------------
__global__ __launch_bounds__(256) void ln_kernel(const float* __restrict__ in,
                                                 const float* __restrict__ g,
                                                 const float* __restrict__ b,
                                                 float* __restrict__ out) {
    int row = blockIdx.x, tid = threadIdx.x;
    const float* rp = in + (size_t)row * 512;
    float a0 = rp[tid], a1 = rp[tid + 256];
    float s = a0 + a1, s2 = a0 * a0 + a1 * a1;
#pragma unroll
    for (int off = 16; off; off >>= 1) {
        s  += __shfl_down_sync(0xffffffffu, s, off);
        s2 += __shfl_down_sync(0xffffffffu, s2, off);
    }
    __shared__ float rs[8], rs2[8];
    __shared__ float mean_s, inv_s;
    if ((tid & 31) == 0) { rs[tid >> 5] = s; rs2[tid >> 5] = s2; }
    __syncthreads();
    if (tid == 0) {
        float S = 0, S2 = 0;
#pragma unroll
        for (int w = 0; w < 8; w++) { S += rs[w]; S2 += rs2[w]; }
        float m = S * (1.0f / 512.0f);
        float var = fmaxf(S2 * (1.0f / 512.0f) - m * m, 0.0f);
        mean_s = m;
        inv_s = rsqrtf(var + 1e-5f);
    }
    __syncthreads();
    out[(size_t)row * 512 + tid]       = (a0 - mean_s) * inv_s * g[tid] + b[tid];
    out[(size_t)row * 512 + tid + 256] = (a1 - mean_s) * inv_s * g[tid + 256] + b[tid + 256];
}

// ---------------- rms norm --------------------------------------------------
__global__ __launch_bounds__(256) void rms_kernel(const float* __restrict__ in,
                                                  float* __restrict__ out) {
    int row = blockIdx.x, tid = threadIdx.x;
    const float* rp = in + (size_t)row * 512;
    float a0 = rp[tid], a1 = rp[tid + 256];
    float s2 = a0 * a0 + a1 * a1;
#pragma unroll
    for (int off = 16; off; off >>= 1) s2 += __shfl_down_sync(0xffffffffu, s2, off);
    __shared__ float rs2[8];
    __shared__ float inv_s;
    if ((tid & 31) == 0) rs2[tid >> 5] = s2;
    __syncthreads();
    if (tid == 0) {
        float S2 = 0;
#pragma unroll
        for (int w = 0; w < 8; w++) S2 += rs2[w];
        inv_s = rsqrtf(S2 * (1.0f / 512.0f) + 1e-6f);
    }
    __syncthreads();
    out[(size_t)row * 512 + tid]       = a0 * inv_s;
    out[(size_t)row * 512 + tid + 256] = a1 * inv_s;
}

// ---------------- final projection + tanh(coord temp) -----------------------
__global__ __launch_bounds__(256) void zout_kernel(const float* __restrict__ hrms,
                                                   const float* __restrict__ wout,
                                                   const float* __restrict__ ct,
                                                   float* __restrict__ z) {
    int token = blockIdx.x, tid = threadIdx.x;
    __shared__ float xs[512];
    __shared__ float ps[256];
    const float* rp = hrms + (size_t)token * 512;
    xs[tid] = rp[tid];
    xs[tid + 256] = rp[tid + 256];
    __syncthreads();
    int n = tid & 31, g = tid >> 5;
    const float* wr = wout + n * 512 + g * 64;
    const float* xr = xs + g * 64;
    float p = 0.f;
#pragma unroll
    for (int d = 0; d < 64; d++) p += xr[d] * wr[d];
    ps[tid] = p;
    __syncthreads();
    if (tid < 32) {
        float s = 0.f;
#pragma unroll
        for (int gg = 0; gg < 8; gg++) s += ps[gg * 32 + tid];
        float c = ct[tid];
        float sp = log1pf(expf(c));
        z[(size_t)token * 32 + tid] = tanhf(s / (sp + 1e-4f));
    }
}

// ---------------- host ------------------------------------------------------
static float* sym_addr(const void* symbol) {
    void* p = nullptr;
    cudaGetSymbolAddress(&p, symbol);
    return (float*)p;
}

extern "C" void kernel_launch(void* const* d_in, const int* in_sizes, int n_in,
                              void* d_out, int out_size) {
    const float* x     = (const float*)d_in[0];
    const float* qp    = (const float*)d_in[1];
    const float* kp    = (const float*)d_in[2];
    const float* wv    = (const float*)d_in[3];
    const float* wproj = (const float*)d_in[4];
    const float* qgain = (const float*)d_in[5];
    const float* ew0   = (const float*)d_in[6];
    const float* g1    = (const float*)d_in[7];
    const float* b1    = (const float*)d_in[8];
    const float* ew1   = (const float*)d_in[9];
    const float* g2    = (const float*)d_in[10];
    const float* b2    = (const float*)d_in[11];
    const float* ew2   = (const float*)d_in[12];
    const float* ewout = (const float*)d_in[13];
    const float* ct    = (const float*)d_in[14];
    float* z = (float*)d_out;

    float* wqk   = sym_addr(g_wqk);
    float* qkraw = sym_addr(g_qkraw);
    float* v     = sym_addr(g_v);
    float* y     = sym_addr(g_y);
    float* h     = sym_addr(g_h);
    float* he0   = sym_addr(g_he0);
    float* lnb   = sym_addr(g_ln);
    float* he1   = sym_addr(g_he1);
    float* he2   = sym_addr(g_he2);
    float* hrms  = sym_addr(g_hrms);

    dim3 ggrid(8, 64); // N/64, M/64 for M=4096, N=512

    trig_table_kernel<<<256, 128>>>();
    prep_wqk_kernel<<<512, 256>>>(qp, kp);
    gemm_nt_kernel<<<ggrid, 256>>>(x, wqk, nullptr, qkraw, 512, 512, 0);
    rope_kernel<<<4096, 256>>>(qkraw, qgain);
    gemm_nt_kernel<<<ggrid, 256>>>(x, wv, nullptr, v, 512, 512, 0);
    attn_kernel<<<dim3(16, 16), 128>>>();
    gemm_nt_kernel<<<ggrid, 256>>>(y, wproj, x, h, 512, 512, 1);
    gemm_nt_kernel<<<ggrid, 256>>>(h, ew0, nullptr, he0, 512, 512, 0);
    ln_kernel<<<4096, 256>>>(he0, g1, b1, lnb);
    gemm_nt_kernel<<<ggrid, 256>>>(lnb, ew1, h, he1, 512, 512, 2);
    ln_kernel<<<4096, 256>>>(he1, g2, b2, lnb);
    gemm_nt_kernel<<<ggrid, 256>>>(lnb, ew2, he1, he2, 512, 512, 2);
    rms_kernel<<<4096, 256>>>(he2, hrms);
    zout_kernel<<<4096, 256>>>(hrms, ewout, ct, z);
}

// round 2
// speedup vs baseline: 1.0952x; 1.0952x over previous
#include <cuda_runtime.h>
#include <math.h>

#define T_SEQ 2048
#define NTOK  4096
#define DM    512
#define NH    8
#define DH    64
#define DP    32

typedef unsigned long long ull;

// ---------------- f32x2 packed helpers (SASS FFMA2 path) --------------------
__device__ __forceinline__ ull fma2(ull a, ull b, ull c) {
    ull d; asm("fma.rn.f32x2 %0,%1,%2,%3;" : "=l"(d) : "l"(a), "l"(b), "l"(c));
    return d;
}
__device__ __forceinline__ ull mul2(ull a, ull b) {
    ull d; asm("mul.rn.f32x2 %0,%1,%2;" : "=l"(d) : "l"(a), "l"(b));
    return d;
}
__device__ __forceinline__ ull dup2(float a) {
    ull d; asm("mov.b64 %0,{%1,%1};" : "=l"(d) : "f"(a));
    return d;
}
__device__ __forceinline__ float2 unpk(ull a) {
    float2 f; asm("mov.b64 {%0,%1},%2;" : "=f"(f.x), "=f"(f.y) : "l"(a));
    return f;
}

// ---------------- scratch (device globals; no allocations allowed) ----------
__device__ __align__(16) float g_wqk[512 * 512];
__device__ __align__(16) float g_qkraw[NTOK * 512];
__device__ __align__(16) float g_q[16 * T_SEQ * DP];
__device__ __align__(16) float g_k[16 * T_SEQ * DP];
__device__ __align__(16) float g_v[NTOK * DM];
__device__ __align__(16) float g_y[NTOK * DM];
__device__ __align__(16) float g_h[NTOK * DM];
__device__ __align__(16) float g_he0[NTOK * DM];
__device__ __align__(16) float g_ln[NTOK * DM];
__device__ __align__(16) float g_he1[NTOK * DM];
__device__ __align__(16) float g_he2[NTOK * DM];
__device__ __align__(16) float g_hrms[NTOK * DM];
__device__ __align__(16) float g_cos[T_SEQ * 16];
__device__ __align__(16) float g_sin[T_SEQ * 16];

// ---------------- RoPE trig table (double precision, fast-math-proof) -------
__global__ void trig_table_kernel() {
    int idx = blockIdx.x * blockDim.x + threadIdx.x;
    if (idx >= T_SEQ * 16) return;
    int t = idx >> 4, i = idx & 15;
    double p = pow(10000.0, (double)i / 16.0);
    float pf = (float)p;
    float freq = 1.0f / pf;
    float ang = (float)t * freq;
    g_cos[idx] = (float)cos((double)ang);
    g_sin[idx] = (float)sin((double)ang);
}

// ---------------- pack q_projs/k_projs [h][d][o] -> W[n][d] -----------------
__global__ void prep_wqk_kernel(const float* __restrict__ qp,
                                const float* __restrict__ kp) {
    int n = blockIdx.x;
    const float* src = (n < 256) ? qp : kp;
    int nn = n & 255;
    int h = nn >> 5, o = nn & 31;
    for (int d = threadIdx.x; d < 512; d += blockDim.x)
        g_wqk[n * 512 + d] = src[h * 16384 + d * 32 + o];
}

// ---------------- FFMA2 GEMM: C[m,n] = sum_k A[m,k]*W[n,k] ------------------
// Block tile 128x64, ktile 32, 128 threads, 8x8 microtile (f32x2 packed).
// epi: 0 = none, 1 = C = R + acc, 2 = C = R + silu(acc)
#define GBM 128
#define GBN 64
#define GBK 32
__global__ __launch_bounds__(128) void gemm2_kernel(
    const float* __restrict__ A, const float* __restrict__ W,
    const float* __restrict__ R, float* __restrict__ C,
    int K, int N, int epi)
{
    __shared__ __align__(16) float As[GBK][GBM];   // 16 KB
    __shared__ __align__(16) float Bs[GBK][GBN];   // 8 KB
    int t = threadIdx.x;
    int bm = blockIdx.y * GBM, bn = blockIdx.x * GBN;
    int tx = t & 7, ty = t >> 3;

    const float* Ap = A + (size_t)(bm + t) * K;
    int bc = t >> 1, bkh = (t & 1) * 16;
    const float* Wp = W + (size_t)(bn + bc) * K + bkh;

    float4 ar[8], br[4];
#pragma unroll
    for (int i = 0; i < 8; i++) ar[i] = *(const float4*)(Ap + i * 4);
#pragma unroll
    for (int i = 0; i < 4; i++) br[i] = *(const float4*)(Wp + i * 4);

    ull acc[8][4];
#pragma unroll
    for (int i = 0; i < 8; i++)
#pragma unroll
        for (int j = 0; j < 4; j++) acc[i][j] = 0ull;

    int nk = K / GBK;
    for (int kt = 0; kt < nk; kt++) {
        __syncthreads();
#pragma unroll
        for (int i = 0; i < 8; i++) {
            As[i * 4 + 0][t] = ar[i].x; As[i * 4 + 1][t] = ar[i].y;
            As[i * 4 + 2][t] = ar[i].z; As[i * 4 + 3][t] = ar[i].w;
        }
#pragma unroll
        for (int i = 0; i < 4; i++) {
            Bs[bkh + i * 4 + 0][bc] = br[i].x; Bs[bkh + i * 4 + 1][bc] = br[i].y;
            Bs[bkh + i * 4 + 2][bc] = br[i].z; Bs[bkh + i * 4 + 3][bc] = br[i].w;
        }
        __syncthreads();
        if (kt + 1 < nk) {
            const float* An = Ap + (kt + 1) * GBK;
            const float* Wn = Wp + (kt + 1) * GBK;
#pragma unroll
            for (int i = 0; i < 8; i++) ar[i] = *(const float4*)(An + i * 4);
#pragma unroll
            for (int i = 0; i < 4; i++) br[i] = *(const float4*)(Wn + i * 4);
        }
#pragma unroll
        for (int kk = 0; kk < GBK; kk++) {
            float4 a0 = *(const float4*)&As[kk][ty * 8];
            float4 a1 = *(const float4*)&As[kk][ty * 8 + 4];
            ulonglong2 b0 = *(const ulonglong2*)&Bs[kk][tx * 8];
            ulonglong2 b1 = *(const ulonglong2*)&Bs[kk][tx * 8 + 4];
            ull ad0 = dup2(a0.x), ad1 = dup2(a0.y), ad2 = dup2(a0.z), ad3 = dup2(a0.w);
            ull ad4 = dup2(a1.x), ad5 = dup2(a1.y), ad6 = dup2(a1.z), ad7 = dup2(a1.w);
            acc[0][0] = fma2(ad0, b0.x, acc[0][0]); acc[0][1] = fma2(ad0, b0.y, acc[0][1]);
            acc[0][2] = fma2(ad0, b1.x, acc[0][2]); acc[0][3] = fma2(ad0, b1.y, acc[0][3]);
            acc[1][0] = fma2(ad1, b0.x, acc[1][0]); acc[1][1] = fma2(ad1, b0.y, acc[1][1]);
            acc[1][2] = fma2(ad1, b1.x, acc[1][2]); acc[1][3] = fma2(ad1, b1.y, acc[1][3]);
            acc[2][0] = fma2(ad2, b0.x, acc[2][0]); acc[2][1] = fma2(ad2, b0.y, acc[2][1]);
            acc[2][2] = fma2(ad2, b1.x, acc[2][2]); acc[2][3] = fma2(ad2, b1.y, acc[2][3]);
            acc[3][0] = fma2(ad3, b0.x, acc[3][0]); acc[3][1] = fma2(ad3, b0.y, acc[3][1]);
            acc[3][2] = fma2(ad3, b1.x, acc[3][2]); acc[3][3] = fma2(ad3, b1.y, acc[3][3]);
            acc[4][0] = fma2(ad4, b0.x, acc[4][0]); acc[4][1] = fma2(ad4, b0.y, acc[4][1]);
            acc[4][2] = fma2(ad4, b1.x, acc[4][2]); acc[4][3] = fma2(ad4, b1.y, acc[4][3]);
            acc[5][0] = fma2(ad5, b0.x, acc[5][0]); acc[5][1] = fma2(ad5, b0.y, acc[5][1]);
            acc[5][2] = fma2(ad5, b1.x, acc[5][2]); acc[5][3] = fma2(ad5, b1.y, acc[5][3]);
            acc[6][0] = fma2(ad6, b0.x, acc[6][0]); acc[6][1] = fma2(ad6, b0.y, acc[6][1]);
            acc[6][2] = fma2(ad6, b1.x, acc[6][2]); acc[6][3] = fma2(ad6, b1.y, acc[6][3]);
            acc[7][0] = fma2(ad7, b0.x, acc[7][0]); acc[7][1] = fma2(ad7, b0.y, acc[7][1]);
            acc[7][2] = fma2(ad7, b1.x, acc[7][2]); acc[7][3] = fma2(ad7, b1.y, acc[7][3]);
        }
    }

#pragma unroll
    for (int i = 0; i < 8; i++) {
        int row = bm + ty * 8 + i;
        int col = bn + tx * 8;
        size_t idx = (size_t)row * N + col;
        float2 p0 = unpk(acc[i][0]), p1 = unpk(acc[i][1]);
        float2 p2 = unpk(acc[i][2]), p3 = unpk(acc[i][3]);
        float v[8] = {p0.x, p0.y, p1.x, p1.y, p2.x, p2.y, p3.x, p3.y};
        if (epi == 1) {
            float4 r0 = *(const float4*)(R + idx);
            float4 r1 = *(const float4*)(R + idx + 4);
            v[0] += r0.x; v[1] += r0.y; v[2] += r0.z; v[3] += r0.w;
            v[4] += r1.x; v[5] += r1.y; v[6] += r1.z; v[7] += r1.w;
        } else if (epi == 2) {
            float4 r0 = *(const float4*)(R + idx);
            float4 r1 = *(const float4*)(R + idx + 4);
            float rr[8] = {r0.x, r0.y, r0.z, r0.w, r1.x, r1.y, r1.z, r1.w};
#pragma unroll
            for (int j = 0; j < 8; j++) {
                float sg = 1.0f / (1.0f + expf(-v[j]));
                v[j] = rr[j] + v[j] * sg;
            }
        }
        float4 o0 = {v[0], v[1], v[2], v[3]};
        float4 o1 = {v[4], v[5], v[6], v[7]};
        *(float4*)(C + idx) = o0;
        *(float4*)(C + idx + 4) = o1;
    }
}

// ---------------- RoPE + gain + score-scale fold ----------------------------
__global__ __launch_bounds__(256) void rope_kernel(const float* __restrict__ qkraw,
                                                   const float* __restrict__ gain) {
    int token = blockIdx.x;
    int b = token >> 11, t = token & 2047;
    int tid = threadIdx.x;
    int h = tid >> 5, o = tid & 31, i = o & 15;
    float c = g_cos[t * 16 + i];
    float s = g_sin[t * 16 + i];
    const float* row = qkraw + (size_t)token * 512;
    size_t oidx = ((size_t)(b * 8 + h) * T_SEQ + t) * DP + o;

    float q1 = row[h * 32 + i], q2 = row[h * 32 + i + 16];
    float qv = (o < 16) ? (q1 * c - q2 * s) : (q2 * c + q1 * s);
    g_q[oidx] = qv * (gain[h] * 0.17677669529663687f);

    float k1 = row[256 + h * 32 + i], k2 = row[256 + h * 32 + i + 16];
    g_k[oidx] = (o < 16) ? (k1 * c - k2 * s) : (k2 * c + k1 * s);
}

// ---------------- flash attention (f32x2) + self-align epilogue -------------
__global__ __launch_bounds__(128, 1) void attn_kernel() {
    __shared__ __align__(16) float ks[128 * 32];
    __shared__ __align__(16) float vs[128 * 64];
    int bh = blockIdx.y, b = bh >> 3, h = bh & 7;
    int tileIdx = (int)gridDim.x - 1 - (int)blockIdx.x;
    int tid = threadIdx.x;
    int r = tileIdx * 128 + tid;

    ull qp[16];
    {
        const ulonglong2* qr = (const ulonglong2*)(g_q + ((size_t)bh * T_SEQ + r) * DP);
#pragma unroll
        for (int i = 0; i < 8; i++) {
            ulonglong2 t2 = qr[i];
            qp[2 * i] = t2.x; qp[2 * i + 1] = t2.y;
        }
    }
    ull accp[32];
#pragma unroll
    for (int d = 0; d < 32; d++) accp[d] = 0ull;
    float mrow = -3.0e38f, l = 0.f;

    int ntiles = tileIdx + 1;
    for (int tile = 0; tile < ntiles; tile++) {
        int j0 = tile * 128;
        {
            const float4* src = (const float4*)(g_k + ((size_t)bh * T_SEQ + j0) * DP);
            float4* dst = (float4*)ks;
#pragma unroll
            for (int i = 0; i < 8; i++) dst[tid + 128 * i] = src[tid + 128 * i];
            float4* vd = (float4*)vs;
#pragma unroll
            for (int i = 0; i < 16; i++) {
                int idx = tid + 128 * i;
                int row = idx >> 4, seg = idx & 15;
                vd[idx] = *(const float4*)(g_v + ((size_t)(b * T_SEQ + j0 + row)) * DM + h * DH + seg * 4);
            }
        }
        __syncthreads();

        for (int jc = 0; jc < 128; jc += 16) {
            float sc[16];
            float cmax = -3.0e38f;
#pragma unroll
            for (int jj = 0; jj < 16; jj++) {
                const ulonglong2* kr = (const ulonglong2*)(ks + (jc + jj) * 32);
                ull s0 = 0ull, s1 = 0ull;
#pragma unroll
                for (int i = 0; i < 8; i++) {
                    ulonglong2 kv = kr[i];
                    s0 = fma2(qp[2 * i], kv.x, s0);
                    s1 = fma2(qp[2 * i + 1], kv.y, s1);
                }
                float2 f0 = unpk(s0), f1 = unpk(s1);
                float s = (f0.x + f0.y) + (f1.x + f1.y);
                s = (j0 + jc + jj <= r) ? s : -3.0e38f;
                sc[jj] = s;
                cmax = fmaxf(cmax, s);
            }
            float mnew = fmaxf(mrow, cmax);
            float corr = __expf(mrow - mnew);
            float psum = 0.f;
#pragma unroll
            for (int jj = 0; jj < 16; jj++) { sc[jj] = __expf(sc[jj] - mnew); psum += sc[jj]; }
            l = l * corr + psum;
            mrow = mnew;
            ull corr2 = dup2(corr);
#pragma unroll
            for (int d = 0; d < 32; d++) accp[d] = mul2(accp[d], corr2);
#pragma unroll
            for (int jj = 0; jj < 16; jj++) {
                ull pj2 = dup2(sc[jj]);
                const ulonglong2* vr = (const ulonglong2*)(vs + (jc + jj) * 64);
#pragma unroll
                for (int d4 = 0; d4 < 16; d4++) {
                    ulonglong2 vv = vr[d4];
                    accp[2 * d4]     = fma2(pj2, vv.x, accp[2 * d4]);
                    accp[2 * d4 + 1] = fma2(pj2, vv.y, accp[2 * d4 + 1]);
                }
            }
        }
        __syncthreads();
    }

    float acc[64];
#pragma unroll
    for (int i = 0; i < 32; i++) {
        float2 f = unpk(accp[i]);
        acc[2 * i] = f.x; acc[2 * i + 1] = f.y;
    }
    float invl = 1.f / l;
#pragma unroll
    for (int d = 0; d < 64; d++) acc[d] *= invl;
    const float* vrow = g_v + ((size_t)(b * T_SEQ + r)) * DM + h * DH;
    float n2 = 0.f;
#pragma unroll
    for (int d4 = 0; d4 < 16; d4++) {
        float4 vv = *(const float4*)(vrow + 4 * d4);
        n2 += vv.x * vv.x + vv.y * vv.y + vv.z * vv.z + vv.w * vv.w;
    }
    float rn = 1.f / fmaxf(sqrtf(n2), 1e-12f);
    float proj = 0.f;
#pragma unroll
    for (int d4 = 0; d4 < 16; d4++) {
        float4 vv = *(const float4*)(vrow + 4 * d4);
        proj += acc[4 * d4] * vv.x + acc[4 * d4 + 1] * vv.y
              + acc[4 * d4 + 2] * vv.z + acc[4 * d4 + 3] * vv.w;
    }
    proj *= rn;
    float prn = proj * rn;
    float* yrow = g_y + ((size_t)(b * T_SEQ + r)) * DM + h * DH;
#pragma unroll
    for (int d4 = 0; d4 < 16; d4++) {
        float4 vv = *(const float4*)(vrow + 4 * d4);
        float4 o;
        o.x = acc[4 * d4]     - prn * vv.x;
        o.y = acc[4 * d4 + 1] - prn * vv.y;
        o.z = acc[4 * d4 + 2] - prn * vv.z;
        o.w = acc[4 * d4 + 3] - prn * vv.w;
        *(float4*)(yrow + 4 * d4) = o;
    }
}

// ---------------- layernorm ------------------------------------------------
__global__ __launch_bounds__(256) void ln_kernel(const float* __restrict__ in,
                                                 const float* __restrict__ g,
                                                 const float* __restrict__ b,
                                                 float* __restrict__ out) {
    int row = blockIdx.x, tid = threadIdx.x;
    const float* rp = in + (size_t)row * 512;
    float a0 = rp[tid], a1 = rp[tid + 256];
    float s = a0 + a1, s2 = a0 * a0 + a1 * a1;
#pragma unroll
    for (int off = 16; off; off >>= 1) {
        s  += __shfl_down_sync(0xffffffffu, s, off);
        s2 += __shfl_down_sync(0xffffffffu, s2, off);
    }
    __shared__ float rs[8], rs2[8];
    __shared__ float mean_s, inv_s;
    if ((tid & 31) == 0) { rs[tid >> 5] = s; rs2[tid >> 5] = s2; }
    __syncthreads();
    if (tid == 0) {
        float S = 0, S2 = 0;
#pragma unroll
        for (int w = 0; w < 8; w++) { S += rs[w]; S2 += rs2[w]; }
        float m = S * (1.0f / 512.0f);
        float var = fmaxf(S2 * (1.0f / 512.0f) - m * m, 0.0f);
        mean_s = m;
        inv_s = rsqrtf(var + 1e-5f);
    }
    __syncthreads();
    out[(size_t)row * 512 + tid]       = (a0 - mean_s) * inv_s * g[tid] + b[tid];
    out[(size_t)row * 512 + tid + 256] = (a1 - mean_s) * inv_s * g[tid + 256] + b[tid + 256];
}

// ---------------- rms norm --------------------------------------------------
__global__ __launch_bounds__(256) void rms_kernel(const float* __restrict__ in,
                                                  float* __restrict__ out) {
    int row = blockIdx.x, tid = threadIdx.x;
    const float* rp = in + (size_t)row * 512;
    float a0 = rp[tid], a1 = rp[tid + 256];
    float s2 = a0 * a0 + a1 * a1;
#pragma unroll
    for (int off = 16; off; off >>= 1) s2 += __shfl_down_sync(0xffffffffu, s2, off);
    __shared__ float rs2[8];
    __shared__ float inv_s;
    if ((tid & 31) == 0) rs2[tid >> 5] = s2;
    __syncthreads();
    if (tid == 0) {
        float S2 = 0;
#pragma unroll
        for (int w = 0; w < 8; w++) S2 += rs2[w];
        inv_s = rsqrtf(S2 * (1.0f / 512.0f) + 1e-6f);
    }
    __syncthreads();
    out[(size_t)row * 512 + tid]       = a0 * inv_s;
    out[(size_t)row * 512 + tid + 256] = a1 * inv_s;
}

// ---------------- final projection + tanh(coord temp) -----------------------
__global__ __launch_bounds__(256) void zout_kernel(const float* __restrict__ hrms,
                                                   const float* __restrict__ wout,
                                                   const float* __restrict__ ct,
                                                   float* __restrict__ z) {
    int token = blockIdx.x, tid = threadIdx.x;
    __shared__ float xs[512];
    __shared__ float ps[256];
    const float* rp = hrms + (size_t)token * 512;
    xs[tid] = rp[tid];
    xs[tid + 256] = rp[tid + 256];
    __syncthreads();
    int n = tid & 31, g = tid >> 5;
    const float* wr = wout + n * 512 + g * 64;
    const float* xr = xs + g * 64;
    float p = 0.f;
#pragma unroll
    for (int d = 0; d < 64; d++) p += xr[d] * wr[d];
    ps[tid] = p;
    __syncthreads();
    if (tid < 32) {
        float s = 0.f;
#pragma unroll
        for (int gg = 0; gg < 8; gg++) s += ps[gg * 32 + tid];
        float c = ct[tid];
        float sp = log1pf(expf(c));
        z[(size_t)token * 32 + tid] = tanhf(s / (sp + 1e-4f));
    }
}

// ---------------- host ------------------------------------------------------
static float* sym_addr(const void* symbol) {
    void* p = nullptr;
    cudaGetSymbolAddress(&p, symbol);
    return (float*)p;
}

extern "C" void kernel_launch(void* const* d_in, const int* in_sizes, int n_in,
                              void* d_out, int out_size) {
    const float* x     = (const float*)d_in[0];
    const float* qp    = (const float*)d_in[1];
    const float* kp    = (const float*)d_in[2];
    const float* wv    = (const float*)d_in[3];
    const float* wproj = (const float*)d_in[4];
    const float* qgain = (const float*)d_in[5];
    const float* ew0   = (const float*)d_in[6];
    const float* g1    = (const float*)d_in[7];
    const float* b1    = (const float*)d_in[8];
    const float* ew1   = (const float*)d_in[9];
    const float* g2    = (const float*)d_in[10];
    const float* b2    = (const float*)d_in[11];
    const float* ew2   = (const float*)d_in[12];
    const float* ewout = (const float*)d_in[13];
    const float* ct    = (const float*)d_in[14];
    float* z = (float*)d_out;

    float* wqk   = sym_addr(g_wqk);
    float* qkraw = sym_addr(g_qkraw);
    float* v     = sym_addr(g_v);
    float* y     = sym_addr(g_y);
    float* h     = sym_addr(g_h);
    float* he0   = sym_addr(g_he0);
    float* lnb   = sym_addr(g_ln);
    float* he1   = sym_addr(g_he1);
    float* he2   = sym_addr(g_he2);
    float* hrms  = sym_addr(g_hrms);

    dim3 ggrid(8, 32); // N/64, M/128 for M=4096, N=512

    trig_table_kernel<<<256, 128>>>();
    prep_wqk_kernel<<<512, 256>>>(qp, kp);
    gemm2_kernel<<<ggrid, 128>>>(x, wqk, nullptr, qkraw, 512, 512, 0);
    rope_kernel<<<4096, 256>>>(qkraw, qgain);
    gemm2_kernel<<<ggrid, 128>>>(x, wv, nullptr, v, 512, 512, 0);
    attn_kernel<<<dim3(16, 16), 128>>>();
    gemm2_kernel<<<ggrid, 128>>>(y, wproj, x, h, 512, 512, 1);
    gemm2_kernel<<<ggrid, 128>>>(h, ew0, nullptr, he0, 512, 512, 0);
    ln_kernel<<<4096, 256>>>(he0, g1, b1, lnb);
    gemm2_kernel<<<ggrid, 128>>>(lnb, ew1, h, he1, 512, 512, 2);
    ln_kernel<<<4096, 256>>>(he1, g2, b2, lnb);
    gemm2_kernel<<<ggrid, 128>>>(lnb, ew2, he1, he2, 512, 512, 2);
    rms_kernel<<<4096, 256>>>(he2, hrms);
    zout_kernel<<<4096, 256>>>(hrms, ewout, ct, z);
}

// round 4
// speedup vs baseline: 1.3301x; 1.2144x over previous
#include <cuda_runtime.h>
#include <cuda_bf16.h>
#include <math.h>
#include <stdint.h>

#define T_SEQ 2048
#define NTOK  4096
#define DM    512
#define NH    8
#define DH    64
#define DP    32

typedef unsigned long long ull;

// ---------------- f32x2 packed helpers --------------------------------------
__device__ __forceinline__ ull fma2(ull a, ull b, ull c) {
    ull d; asm("fma.rn.f32x2 %0,%1,%2,%3;" : "=l"(d) : "l"(a), "l"(b), "l"(c));
    return d;
}
__device__ __forceinline__ ull mul2(ull a, ull b) {
    ull d; asm("mul.rn.f32x2 %0,%1,%2;" : "=l"(d) : "l"(a), "l"(b));
    return d;
}
__device__ __forceinline__ ull dup2(float a) {
    ull d; asm("mov.b64 %0,{%1,%1};" : "=l"(d) : "f"(a));
    return d;
}
__device__ __forceinline__ float2 unpk(ull a) {
    float2 f; asm("mov.b64 {%0,%1},%2;" : "=f"(f.x), "=f"(f.y) : "l"(a));
    return f;
}

// ---------------- mma helpers ------------------------------------------------
__device__ __forceinline__ uint32_t smem_u32(const void* p) {
    uint32_t a;
    asm("{ .reg .u64 t; cvta.to.shared.u64 t, %1; cvt.u32.u64 %0, t; }"
        : "=r"(a) : "l"(p));
    return a;
}
__device__ __forceinline__ void ldsm4(uint32_t& r0, uint32_t& r1, uint32_t& r2,
                                      uint32_t& r3, uint32_t addr) {
    asm volatile("ldmatrix.sync.aligned.m8n8.x4.shared.b16 {%0,%1,%2,%3}, [%4];"
        : "=r"(r0), "=r"(r1), "=r"(r2), "=r"(r3) : "r"(addr));
}
__device__ __forceinline__ void mma16816(float& c0, float& c1, float& c2, float& c3,
                                         uint32_t a0, uint32_t a1, uint32_t a2,
                                         uint32_t a3, uint32_t b0, uint32_t b1) {
    asm volatile("mma.sync.aligned.m16n8k16.row.col.f32.bf16.bf16.f32 "
        "{%0,%1,%2,%3}, {%4,%5,%6,%7}, {%8,%9}, {%0,%1,%2,%3};"
        : "+f"(c0), "+f"(c1), "+f"(c2), "+f"(c3)
        : "r"(a0), "r"(a1), "r"(a2), "r"(a3), "r"(b0), "r"(b1));
}

// ---------------- scratch (device globals) ----------------------------------
__device__ __align__(16) float g_wqk[512 * 512];
__device__ __align__(16) float g_qkraw[NTOK * 512];
__device__ __align__(16) float g_q[16 * T_SEQ * DP];
__device__ __align__(16) float g_k[16 * T_SEQ * DP];
__device__ __align__(16) float g_v[NTOK * DM];
__device__ __align__(16) float g_y[NTOK * DM];
__device__ __align__(16) float g_h[NTOK * DM];
__device__ __align__(16) float g_he0[NTOK * DM];
__device__ __align__(16) float g_ln[NTOK * DM];
__device__ __align__(16) float g_he1[NTOK * DM];
__device__ __align__(16) float g_he2[NTOK * DM];
__device__ __align__(16) float g_hrms[NTOK * DM];
__device__ __align__(16) float g_cos[T_SEQ * 16];
__device__ __align__(16) float g_sin[T_SEQ * 16];

// bf16 split buffers: activations [4096][1536], weights [512][1536]
__device__ __align__(16) __nv_bfloat16 g_a16[NTOK * 1536];
__device__ __align__(16) __nv_bfloat16 g_w16qk[512 * 1536];
__device__ __align__(16) __nv_bfloat16 g_w16v[512 * 1536];
__device__ __align__(16) __nv_bfloat16 g_w16p[512 * 1536];
__device__ __align__(16) __nv_bfloat16 g_w16e0[512 * 1536];
__device__ __align__(16) __nv_bfloat16 g_w16e1[512 * 1536];
__device__ __align__(16) __nv_bfloat16 g_w16e2[512 * 1536];

// ---------------- RoPE trig table -------------------------------------------
__global__ void trig_table_kernel() {
    int idx = blockIdx.x * blockDim.x + threadIdx.x;
    if (idx >= T_SEQ * 16) return;
    int t = idx >> 4, i = idx & 15;
    double p = pow(10000.0, (double)i / 16.0);
    float pf = (float)p;
    float freq = 1.0f / pf;
    float ang = (float)t * freq;
    g_cos[idx] = (float)cos((double)ang);
    g_sin[idx] = (float)sin((double)ang);
}

// ---------------- pack q_projs/k_projs [h][d][o] -> W[n][d] -----------------
__global__ void prep_wqk_kernel(const float* __restrict__ qp,
                                const float* __restrict__ kp) {
    int n = blockIdx.x;
    const float* src = (n < 256) ? qp : kp;
    int nn = n & 255;
    int h = nn >> 5, o = nn & 31;
    for (int d = threadIdx.x; d < 512; d += blockDim.x)
        g_wqk[n * 512 + d] = src[h * 16384 + d * 32 + o];
}

// ---------------- fp32 -> bf16 split conversions ----------------------------
// activation: [M][512] -> [M][1536] as [hi | lo | hi]
__global__ __launch_bounds__(256) void conv_act_kernel(const float* __restrict__ in,
                                                       __nv_bfloat16* __restrict__ out,
                                                       int M) {
    int idx = blockIdx.x * 256 + threadIdx.x;
    if (idx >= M * 512) return;
    int row = idx >> 9, col = idx & 511;
    float x = in[idx];
    __nv_bfloat16 h = __float2bfloat16(x);
    float r = x - __bfloat162float(h);
    __nv_bfloat16 l = __float2bfloat16(r);
    size_t base = (size_t)row * 1536;
    out[base + col] = h;
    out[base + 512 + col] = l;
    out[base + 1024 + col] = h;
}
// weight: [512][512] -> [512][1536] as [hi | hi | lo]
__global__ __launch_bounds__(256) void conv_w_kernel(const float* __restrict__ in,
                                                     __nv_bfloat16* __restrict__ out) {
    int idx = blockIdx.x * 256 + threadIdx.x;
    int row = idx >> 9, col = idx & 511;
    float x = in[idx];
    __nv_bfloat16 h = __float2bfloat16(x);
    float r = x - __bfloat162float(h);
    __nv_bfloat16 l = __float2bfloat16(r);
    size_t base = (size_t)row * 1536;
    out[base + col] = h;
    out[base + 512 + col] = h;
    out[base + 1024 + col] = l;
}

// ---------------- HMMA GEMM --------------------------------------------------
// C[4096][512] = A16[4096][1536] x W16[512][1536]^T  (bf16 in, fp32 acc)
// Block 128x64, BK=64, 256 threads, 8 warps in 4(m)x2(n), warp tile 32x32.
// epi: 0 none, 1 C=R+acc, 2 C=R+silu(acc)
#define NKT 24
__global__ __launch_bounds__(256) void gemm_mma_kernel(
    const __nv_bfloat16* __restrict__ A16, const __nv_bfloat16* __restrict__ W16,
    const float* __restrict__ R, float* __restrict__ C, int epi)
{
    // A tile: 128 rows x 128B (64 bf16); B tile: 64 rows x 128B
    __shared__ __align__(128) char sm[(128 + 64) * 128];
    uint32_t sb = smem_u32(sm);
    const uint32_t sbB = sb + 128 * 128;

    int tid = threadIdx.x, wid = tid >> 5, lane = tid & 31;
    int bm = blockIdx.y * 128, bn = blockIdx.x * 64;
    int wm = wid >> 1, wn = wid & 1;

    // ---- global load mapping (per thread) ----
    int arow = tid >> 1;                 // A: rows 0..127, 2 threads/row
    int aseg = (tid & 1) << 2;           // seg pairs: this thread does segs aseg..aseg+3? no:
    // A tile = 128 rows x 8 segs(16B). 1024 uint4 / 256 thr = 4 each.
    // thread covers (row = (it*256+tid)>>3, seg = (it*256+tid)&7)
    // B tile = 64 rows x 8 segs = 512 uint4 -> 2 each.
    (void)arow; (void)aseg;
    const __nv_bfloat16* Abase = A16 + (size_t)bm * 1536;
    const __nv_bfloat16* Wbase = W16 + (size_t)bn * 1536;

    uint4 apre[4], bpre[2];
#pragma unroll
    for (int it = 0; it < 4; it++) {
        int idx = it * 256 + tid, row = idx >> 3, seg = idx & 7;
        apre[it] = *(const uint4*)(Abase + (size_t)row * 1536 + seg * 8);
    }
#pragma unroll
    for (int it = 0; it < 2; it++) {
        int idx = it * 256 + tid, row = idx >> 3, seg = idx & 7;
        bpre[it] = *(const uint4*)(Wbase + (size_t)row * 1536 + seg * 8);
    }

    // ---- ldmatrix address precompute ----
    // A frag (per mi): row = wm*32 + mi*16 + (lane&15); 16B-col sel = (lane>=16)?16:0
    uint32_t aAddr[2], aSw[2];
#pragma unroll
    for (int mi = 0; mi < 2; mi++) {
        int row = wm * 32 + mi * 16 + (lane & 15);
        int csel = (lane >> 4) << 4;
        aAddr[mi] = sb + row * 128;
        aSw[mi] = (uint32_t)(csel ^ ((row & 7) << 4));
    }
    // B frag (per g in {0,1} covering n-blocks 2g,2g+1):
    // nrow = wn*32 + g*16 + (lane&7) + ((lane>=16)?8:0); csel = (lane&8)?16:0
    uint32_t bAddr[2], bSw[2];
#pragma unroll
    for (int g = 0; g < 2; g++) {
        int nrow = wn * 32 + g * 16 + (lane & 7) + ((lane >> 4) << 3);
        int csel = (lane & 8) << 1;
        bAddr[g] = sbB + nrow * 128;
        bSw[g] = (uint32_t)(csel ^ ((nrow & 7) << 4));
    }

    float c[2][4][4];
#pragma unroll
    for (int mi = 0; mi < 2; mi++)
#pragma unroll
        for (int ni = 0; ni < 4; ni++)
#pragma unroll
            for (int q = 0; q < 4; q++) c[mi][ni][q] = 0.f;

    for (int kt = 0; kt < NKT; kt++) {
        __syncthreads();
#pragma unroll
        for (int it = 0; it < 4; it++) {
            int idx = it * 256 + tid, row = idx >> 3, seg = idx & 7;
            uint32_t off = (uint32_t)(row * 128 + ((seg * 16) ^ ((row & 7) << 4)));
            *(uint4*)(sm + off) = apre[it];
        }
#pragma unroll
        for (int it = 0; it < 2; it++) {
            int idx = it * 256 + tid, row = idx >> 3, seg = idx & 7;
            uint32_t off = (uint32_t)(row * 128 + ((seg * 16) ^ ((row & 7) << 4)));
            *(uint4*)(sm + 128 * 128 + off) = bpre[it];
        }
        __syncthreads();
        if (kt + 1 < NKT) {
            int kofs = (kt + 1) * 64;
#pragma unroll
            for (int it = 0; it < 4; it++) {
                int idx = it * 256 + tid, row = idx >> 3, seg = idx & 7;
                apre[it] = *(const uint4*)(Abase + (size_t)row * 1536 + kofs + seg * 8);
            }
#pragma unroll
            for (int it = 0; it < 2; it++) {
                int idx = it * 256 + tid, row = idx >> 3, seg = idx & 7;
                bpre[it] = *(const uint4*)(Wbase + (size_t)row * 1536 + kofs + seg * 8);
            }
        }
#pragma unroll
        for (int ks = 0; ks < 4; ks++) {
            uint32_t a0[4], a1[4], b0[4], b1[4];
            ldsm4(a0[0], a0[1], a0[2], a0[3], aAddr[0] + (uint32_t)((ks * 32) ^ aSw[0]));
            ldsm4(a1[0], a1[1], a1[2], a1[3], aAddr[1] + (uint32_t)((ks * 32) ^ aSw[1]));
            ldsm4(b0[0], b0[1], b0[2], b0[3], bAddr[0] + (uint32_t)((ks * 32) ^ bSw[0]));
            ldsm4(b1[0], b1[1], b1[2], b1[3], bAddr[1] + (uint32_t)((ks * 32) ^ bSw[1]));
            // b0 regs: {b0(n0),b1(n0),b0(n1),b1(n1)}; b1 regs: n2,n3
            mma16816(c[0][0][0], c[0][0][1], c[0][0][2], c[0][0][3],
                     a0[0], a0[1], a0[2], a0[3], b0[0], b0[1]);
            mma16816(c[0][1][0], c[0][1][1], c[0][1][2], c[0][1][3],
                     a0[0], a0[1], a0[2], a0[3], b0[2], b0[3]);
            mma16816(c[0][2][0], c[0][2][1], c[0][2][2], c[0][2][3],
                     a0[0], a0[1], a0[2], a0[3], b1[0], b1[1]);
            mma16816(c[0][3][0], c[0][3][1], c[0][3][2], c[0][3][3],
                     a0[0], a0[1], a0[2], a0[3], b1[2], b1[3]);
            mma16816(c[1][0][0], c[1][0][1], c[1][0][2], c[1][0][3],
                     a1[0], a1[1], a1[2], a1[3], b0[0], b0[1]);
            mma16816(c[1][1][0], c[1][1][1], c[1][1][2], c[1][1][3],
                     a1[0], a1[1], a1[2], a1[3], b0[2], b0[3]);
            mma16816(c[1][2][0], c[1][2][1], c[1][2][2], c[1][2][3],
                     a1[0], a1[1], a1[2], a1[3], b1[0], b1[1]);
            mma16816(c[1][3][0], c[1][3][1], c[1][3][2], c[1][3][3],
                     a1[0], a1[1], a1[2], a1[3], b1[2], b1[3]);
        }
    }

    // ---- epilogue ----
    int gq = lane >> 2, tig = lane & 3;
#pragma unroll
    for (int mi = 0; mi < 2; mi++) {
#pragma unroll
        for (int ni = 0; ni < 4; ni++) {
#pragma unroll
            for (int half = 0; half < 2; half++) {
                int row = bm + wm * 32 + mi * 16 + gq + half * 8;
                int col = bn + wn * 32 + ni * 8 + tig * 2;
                size_t o = (size_t)row * 512 + col;
                float v0 = c[mi][ni][half * 2], v1 = c[mi][ni][half * 2 + 1];
                if (epi == 1) {
                    float2 rr = *(const float2*)(R + o);
                    v0 += rr.x; v1 += rr.y;
                } else if (epi == 2) {
                    float2 rr = *(const float2*)(R + o);
                    v0 = rr.x + v0 / (1.0f + expf(-v0));
                    v1 = rr.y + v1 / (1.0f + expf(-v1));
                }
                float2 ov = {v0, v1};
                *(float2*)(C + o) = ov;
            }
        }
    }
}

// ---------------- RoPE + gain + score-scale fold ----------------------------
__global__ __launch_bounds__(256) void rope_kernel(const float* __restrict__ qkraw,
                                                   const float* __restrict__ gain) {
    int token = blockIdx.x;
    int b = token >> 11, t = token & 2047;
    int tid = threadIdx.x;
    int h = tid >> 5, o = tid & 31, i = o & 15;
    float c = g_cos[t * 16 + i];
    float s = g_sin[t * 16 + i];
    const float* row = qkraw + (size_t)token * 512;
    size_t oidx = ((size_t)(b * 8 + h) * T_SEQ + t) * DP + o;

    float q1 = row[h * 32 + i], q2 = row[h * 32 + i + 16];
    float qv = (o < 16) ? (q1 * c - q2 * s) : (q2 * c + q1 * s);
    g_q[oidx] = qv * (gain[h] * 0.17677669529663687f);

    float k1 = row[256 + h * 32 + i], k2 = row[256 + h * 32 + i + 16];
    g_k[oidx] = (o < 16) ? (k1 * c - k2 * s) : (k2 * c + k1 * s);
}

// ---------------- flash attention (f32x2) + self-align epilogue -------------
__global__ __launch_bounds__(128, 1) void attn_kernel() {
    __shared__ __align__(16) float ks[128 * 32];
    __shared__ __align__(16) float vs[128 * 64];
    int bh = blockIdx.y, b = bh >> 3, h = bh & 7;
    int tileIdx = (int)gridDim.x - 1 - (int)blockIdx.x;
    int tid = threadIdx.x;
    int r = tileIdx * 128 + tid;

    ull qp[16];
    {
        const ulonglong2* qr = (const ulonglong2*)(g_q + ((size_t)bh * T_SEQ + r) * DP);
#pragma unroll
        for (int i = 0; i < 8; i++) {
            ulonglong2 t2 = qr[i];
            qp[2 * i] = t2.x; qp[2 * i + 1] = t2.y;
        }
    }
    ull accp[32];
#pragma unroll
    for (int d = 0; d < 32; d++) accp[d] = 0ull;
    float mrow = -3.0e38f, l = 0.f;

    int ntiles = tileIdx + 1;
    for (int tile = 0; tile < ntiles; tile++) {
        int j0 = tile * 128;
        {
            const float4* src = (const float4*)(g_k + ((size_t)bh * T_SEQ + j0) * DP);
            float4* dst = (float4*)ks;
#pragma unroll
            for (int i = 0; i < 8; i++) dst[tid + 128 * i] = src[tid + 128 * i];
            float4* vd = (float4*)vs;
#pragma unroll
            for (int i = 0; i < 16; i++) {
                int idx = tid + 128 * i;
                int row = idx >> 4, seg = idx & 15;
                vd[idx] = *(const float4*)(g_v + ((size_t)(b * T_SEQ + j0 + row)) * DM + h * DH + seg * 4);
            }
        }
        __syncthreads();

        for (int jc = 0; jc < 128; jc += 16) {
            float sc[16];
            float cmax = -3.0e38f;
#pragma unroll
            for (int jj = 0; jj < 16; jj++) {
                const ulonglong2* kr = (const ulonglong2*)(ks + (jc + jj) * 32);
                ull s0 = 0ull, s1 = 0ull;
#pragma unroll
                for (int i = 0; i < 8; i++) {
                    ulonglong2 kv = kr[i];
                    s0 = fma2(qp[2 * i], kv.x, s0);
                    s1 = fma2(qp[2 * i + 1], kv.y, s1);
                }
                float2 f0 = unpk(s0), f1 = unpk(s1);
                float s = (f0.x + f0.y) + (f1.x + f1.y);
                s = (j0 + jc + jj <= r) ? s : -3.0e38f;
                sc[jj] = s;
                cmax = fmaxf(cmax, s);
            }
            float mnew = fmaxf(mrow, cmax);
            float corr = __expf(mrow - mnew);
            float psum = 0.f;
#pragma unroll
            for (int jj = 0; jj < 16; jj++) { sc[jj] = __expf(sc[jj] - mnew); psum += sc[jj]; }
            l = l * corr + psum;
            mrow = mnew;
            ull corr2 = dup2(corr);
#pragma unroll
            for (int d = 0; d < 32; d++) accp[d] = mul2(accp[d], corr2);
#pragma unroll
            for (int jj = 0; jj < 16; jj++) {
                ull pj2 = dup2(sc[jj]);
                const ulonglong2* vr = (const ulonglong2*)(vs + (jc + jj) * 64);
#pragma unroll
                for (int d4 = 0; d4 < 16; d4++) {
                    ulonglong2 vv = vr[d4];
                    accp[2 * d4]     = fma2(pj2, vv.x, accp[2 * d4]);
                    accp[2 * d4 + 1] = fma2(pj2, vv.y, accp[2 * d4 + 1]);
                }
            }
        }
        __syncthreads();
    }

    float acc[64];
#pragma unroll
    for (int i = 0; i < 32; i++) {
        float2 f = unpk(accp[i]);
        acc[2 * i] = f.x; acc[2 * i + 1] = f.y;
    }
    float invl = 1.f / l;
#pragma unroll
    for (int d = 0; d < 64; d++) acc[d] *= invl;
    const float* vrow = g_v + ((size_t)(b * T_SEQ + r)) * DM + h * DH;
    float n2 = 0.f;
#pragma unroll
    for (int d4 = 0; d4 < 16; d4++) {
        float4 vv = *(const float4*)(vrow + 4 * d4);
        n2 += vv.x * vv.x + vv.y * vv.y + vv.z * vv.z + vv.w * vv.w;
    }
    float rn = 1.f / fmaxf(sqrtf(n2), 1e-12f);
    float proj = 0.f;
#pragma unroll
    for (int d4 = 0; d4 < 16; d4++) {
        float4 vv = *(const float4*)(vrow + 4 * d4);
        proj += acc[4 * d4] * vv.x + acc[4 * d4 + 1] * vv.y
              + acc[4 * d4 + 2] * vv.z + acc[4 * d4 + 3] * vv.w;
    }
    proj *= rn;
    float prn = proj * rn;
    float* yrow = g_y + ((size_t)(b * T_SEQ + r)) * DM + h * DH;
#pragma unroll
    for (int d4 = 0; d4 < 16; d4++) {
        float4 vv = *(const float4*)(vrow + 4 * d4);
        float4 o;
        o.x = acc[4 * d4]     - prn * vv.x;
        o.y = acc[4 * d4 + 1] - prn * vv.y;
        o.z = acc[4 * d4 + 2] - prn * vv.z;
        o.w = acc[4 * d4 + 3] - prn * vv.w;
        *(float4*)(yrow + 4 * d4) = o;
    }
}

// ---------------- layernorm ------------------------------------------------
__global__ __launch_bounds__(256) void ln_kernel(const float* __restrict__ in,
                                                 const float* __restrict__ g,
                                                 const float* __restrict__ b,
                                                 float* __restrict__ out) {
    int row = blockIdx.x, tid = threadIdx.x;
    const float* rp = in + (size_t)row * 512;
    float a0 = rp[tid], a1 = rp[tid + 256];
    float s = a0 + a1, s2 = a0 * a0 + a1 * a1;
#pragma unroll
    for (int off = 16; off; off >>= 1) {
        s  += __shfl_down_sync(0xffffffffu, s, off);
        s2 += __shfl_down_sync(0xffffffffu, s2, off);
    }
    __shared__ float rs[8], rs2[8];
    __shared__ float mean_s, inv_s;
    if ((tid & 31) == 0) { rs[tid >> 5] = s; rs2[tid >> 5] = s2; }
    __syncthreads();
    if (tid == 0) {
        float S = 0, S2 = 0;
#pragma unroll
        for (int w = 0; w < 8; w++) { S += rs[w]; S2 += rs2[w]; }
        float m = S * (1.0f / 512.0f);
        float var = fmaxf(S2 * (1.0f / 512.0f) - m * m, 0.0f);
        mean_s = m;
        inv_s = rsqrtf(var + 1e-5f);
    }
    __syncthreads();
    out[(size_t)row * 512 + tid]       = (a0 - mean_s) * inv_s * g[tid] + b[tid];
    out[(size_t)row * 512 + tid + 256] = (a1 - mean_s) * inv_s * g[tid + 256] + b[tid + 256];
}

// ---------------- rms norm --------------------------------------------------
__global__ __launch_bounds__(256) void rms_kernel(const float* __restrict__ in,
                                                  float* __restrict__ out) {
    int row = blockIdx.x, tid = threadIdx.x;
    const float* rp = in + (size_t)row * 512;
    float a0 = rp[tid], a1 = rp[tid + 256];
    float s2 = a0 * a0 + a1 * a1;
#pragma unroll
    for (int off = 16; off; off >>= 1) s2 += __shfl_down_sync(0xffffffffu, s2, off);
    __shared__ float rs2[8];
    __shared__ float inv_s;
    if ((tid & 31) == 0) rs2[tid >> 5] = s2;
    __syncthreads();
    if (tid == 0) {
        float S2 = 0;
#pragma unroll
        for (int w = 0; w < 8; w++) S2 += rs2[w];
        inv_s = rsqrtf(S2 * (1.0f / 512.0f) + 1e-6f);
    }
    __syncthreads();
    out[(size_t)row * 512 + tid]       = a0 * inv_s;
    out[(size_t)row * 512 + tid + 256] = a1 * inv_s;
}

// ---------------- final projection + tanh(coord temp) -----------------------
__global__ __launch_bounds__(256) void zout_kernel(const float* __restrict__ hrms,
                                                   const float* __restrict__ wout,
                                                   const float* __restrict__ ct,
                                                   float* __restrict__ z) {
    int token = blockIdx.x, tid = threadIdx.x;
    __shared__ float xs[512];
    __shared__ float ps[256];
    const float* rp = hrms + (size_t)token * 512;
    xs[tid] = rp[tid];
    xs[tid + 256] = rp[tid + 256];
    __syncthreads();
    int n = tid & 31, g = tid >> 5;
    const float* wr = wout + n * 512 + g * 64;
    const float* xr = xs + g * 64;
    float p = 0.f;
#pragma unroll
    for (int d = 0; d < 64; d++) p += xr[d] * wr[d];
    ps[tid] = p;
    __syncthreads();
    if (tid < 32) {
        float s = 0.f;
#pragma unroll
        for (int gg = 0; gg < 8; gg++) s += ps[gg * 32 + tid];
        float c = ct[tid];
        float sp = log1pf(expf(c));
        z[(size_t)token * 32 + tid] = tanhf(s / (sp + 1e-4f));
    }
}

// ---------------- host ------------------------------------------------------
static float* sym_addr_f(const void* symbol) {
    void* p = nullptr;
    cudaGetSymbolAddress(&p, symbol);
    return (float*)p;
}
static __nv_bfloat16* sym_addr_b(const void* symbol) {
    void* p = nullptr;
    cudaGetSymbolAddress(&p, symbol);
    return (__nv_bfloat16*)p;
}

extern "C" void kernel_launch(void* const* d_in, const int* in_sizes, int n_in,
                              void* d_out, int out_size) {
    const float* x     = (const float*)d_in[0];
    const float* qp    = (const float*)d_in[1];
    const float* kp    = (const float*)d_in[2];
    const float* wv    = (const float*)d_in[3];
    const float* wproj = (const float*)d_in[4];
    const float* qgain = (const float*)d_in[5];
    const float* ew0   = (const float*)d_in[6];
    const float* g1    = (const float*)d_in[7];
    const float* b1    = (const float*)d_in[8];
    const float* ew1   = (const float*)d_in[9];
    const float* g2    = (const float*)d_in[10];
    const float* b2    = (const float*)d_in[11];
    const float* ew2   = (const float*)d_in[12];
    const float* ewout = (const float*)d_in[13];
    const float* ct    = (const float*)d_in[14];
    float* z = (float*)d_out;

    float* wqk   = sym_addr_f(g_wqk);
    float* qkraw = sym_addr_f(g_qkraw);
    float* v     = sym_addr_f(g_v);
    float* y     = sym_addr_f(g_y);
    float* h     = sym_addr_f(g_h);
    float* he0   = sym_addr_f(g_he0);
    float* lnb   = sym_addr_f(g_ln);
    float* he1   = sym_addr_f(g_he1);
    float* he2   = sym_addr_f(g_he2);
    float* hrms  = sym_addr_f(g_hrms);

    __nv_bfloat16* a16   = sym_addr_b(g_a16);
    __nv_bfloat16* wqk16 = sym_addr_b(g_w16qk);
    __nv_bfloat16* wv16  = sym_addr_b(g_w16v);
    __nv_bfloat16* wp16  = sym_addr_b(g_w16p);
    __nv_bfloat16* we016 = sym_addr_b(g_w16e0);
    __nv_bfloat16* we116 = sym_addr_b(g_w16e1);
    __nv_bfloat16* we216 = sym_addr_b(g_w16e2);

    dim3 ggrid(8, 32);   // N/64 = 8, M/128 = 32
    const int WBLK = 512 * 512 / 256;
    const int ABLK = NTOK * 512 / 256;

    trig_table_kernel<<<256, 128>>>();
    prep_wqk_kernel<<<512, 256>>>(qp, kp);
    conv_w_kernel<<<WBLK, 256>>>(wqk, wqk16);
    conv_w_kernel<<<WBLK, 256>>>(wv, wv16);
    conv_w_kernel<<<WBLK, 256>>>(wproj, wp16);
    conv_w_kernel<<<WBLK, 256>>>(ew0, we016);
    conv_w_kernel<<<WBLK, 256>>>(ew1, we116);
    conv_w_kernel<<<WBLK, 256>>>(ew2, we216);

    conv_act_kernel<<<ABLK, 256>>>(x, a16, NTOK);
    gemm_mma_kernel<<<ggrid, 256>>>(a16, wqk16, nullptr, qkraw, 0);
    rope_kernel<<<4096, 256>>>(qkraw, qgain);
    gemm_mma_kernel<<<ggrid, 256>>>(a16, wv16, nullptr, v, 0);
    attn_kernel<<<dim3(16, 16), 128>>>();
    conv_act_kernel<<<ABLK, 256>>>(y, a16, NTOK);
    gemm_mma_kernel<<<ggrid, 256>>>(a16, wp16, x, h, 1);
    conv_act_kernel<<<ABLK, 256>>>(h, a16, NTOK);
    gemm_mma_kernel<<<ggrid, 256>>>(a16, we016, nullptr, he0, 0);
    ln_kernel<<<4096, 256>>>(he0, g1, b1, lnb);
    conv_act_kernel<<<ABLK, 256>>>(lnb, a16, NTOK);
    gemm_mma_kernel<<<ggrid, 256>>>(a16, we116, h, he1, 2);
    ln_kernel<<<4096, 256>>>(he1, g2, b2, lnb);
    conv_act_kernel<<<ABLK, 256>>>(lnb, a16, NTOK);
    gemm_mma_kernel<<<ggrid, 256>>>(a16, we216, he1, he2, 2);
    rms_kernel<<<4096, 256>>>(he2, hrms);
    zout_kernel<<<4096, 256>>>(hrms, ewout, ct, z);
}

// round 5
// speedup vs baseline: 1.4084x; 1.0589x over previous
#include <cuda_runtime.h>
#include <cuda_bf16.h>
#include <math.h>
#include <stdint.h>

#define T_SEQ 2048
#define NTOK  4096
#define DM    512
#define NH    8
#define DH    64
#define DP    32

typedef unsigned long long ull;

// ---------------- f32x2 packed helpers --------------------------------------
__device__ __forceinline__ ull fma2(ull a, ull b, ull c) {
    ull d; asm("fma.rn.f32x2 %0,%1,%2,%3;" : "=l"(d) : "l"(a), "l"(b), "l"(c));
    return d;
}
__device__ __forceinline__ ull mul2(ull a, ull b) {
    ull d; asm("mul.rn.f32x2 %0,%1,%2;" : "=l"(d) : "l"(a), "l"(b));
    return d;
}
__device__ __forceinline__ ull dup2(float a) {
    ull d; asm("mov.b64 %0,{%1,%1};" : "=l"(d) : "f"(a));
    return d;
}
__device__ __forceinline__ float2 unpk(ull a) {
    float2 f; asm("mov.b64 {%0,%1},%2;" : "=f"(f.x), "=f"(f.y) : "l"(a));
    return f;
}

// ---------------- mma / async helpers ----------------------------------------
__device__ __forceinline__ uint32_t smem_u32(const void* p) {
    uint32_t a;
    asm("{ .reg .u64 t; cvta.to.shared.u64 t, %1; cvt.u32.u64 %0, t; }"
        : "=r"(a) : "l"(p));
    return a;
}
__device__ __forceinline__ void cp16(uint32_t dst, const void* src) {
    asm volatile("cp.async.cg.shared.global [%0], [%1], 16;"
        :: "r"(dst), "l"(src) : "memory");
}
__device__ __forceinline__ void ldsm4(uint32_t& r0, uint32_t& r1, uint32_t& r2,
                                      uint32_t& r3, uint32_t addr) {
    asm volatile("ldmatrix.sync.aligned.m8n8.x4.shared.b16 {%0,%1,%2,%3}, [%4];"
        : "=r"(r0), "=r"(r1), "=r"(r2), "=r"(r3) : "r"(addr));
}
__device__ __forceinline__ void mma16816(float& c0, float& c1, float& c2, float& c3,
                                         uint32_t a0, uint32_t a1, uint32_t a2,
                                         uint32_t a3, uint32_t b0, uint32_t b1) {
    asm volatile("mma.sync.aligned.m16n8k16.row.col.f32.bf16.bf16.f32 "
        "{%0,%1,%2,%3}, {%4,%5,%6,%7}, {%8,%9}, {%0,%1,%2,%3};"
        : "+f"(c0), "+f"(c1), "+f"(c2), "+f"(c3)
        : "r"(a0), "r"(a1), "r"(a2), "r"(a3), "r"(b0), "r"(b1));
}

// ---------------- scratch (device globals) ----------------------------------
__device__ __align__(16) float g_wqk[512 * 512];
__device__ __align__(16) float g_qkraw[NTOK * 512];
__device__ __align__(16) float g_q[16 * T_SEQ * DP];
__device__ __align__(16) float g_k[16 * T_SEQ * DP];
__device__ __align__(16) float g_v[NTOK * DM];
__device__ __align__(16) float g_h[NTOK * DM];
__device__ __align__(16) float g_he0[NTOK * DM];
__device__ __align__(16) float g_he1[NTOK * DM];
__device__ __align__(16) float g_he2[NTOK * DM];
__device__ __align__(16) float g_hrms[NTOK * DM];
__device__ __align__(16) float g_cos[T_SEQ * 16];
__device__ __align__(16) float g_sin[T_SEQ * 16];

// activation split buffers (A/B ping-pong): [4096][1536] = [hi|lo|hi]
__device__ __align__(16) __nv_bfloat16 g_a16[NTOK * 1536];
__device__ __align__(16) __nv_bfloat16 g_b16[NTOK * 1536];
// weight split buffers: [512][1536] = [hi|hi|lo]
__device__ __align__(16) __nv_bfloat16 g_w16qk[512 * 1536];
__device__ __align__(16) __nv_bfloat16 g_w16v[512 * 1536];
__device__ __align__(16) __nv_bfloat16 g_w16p[512 * 1536];
__device__ __align__(16) __nv_bfloat16 g_w16e0[512 * 1536];
__device__ __align__(16) __nv_bfloat16 g_w16e1[512 * 1536];
__device__ __align__(16) __nv_bfloat16 g_w16e2[512 * 1536];

// ---------------- RoPE trig table -------------------------------------------
__global__ void trig_table_kernel() {
    int idx = blockIdx.x * blockDim.x + threadIdx.x;
    if (idx >= T_SEQ * 16) return;
    int t = idx >> 4, i = idx & 15;
    double p = pow(10000.0, (double)i / 16.0);
    float pf = (float)p;
    float freq = 1.0f / pf;
    float ang = (float)t * freq;
    g_cos[idx] = (float)cos((double)ang);
    g_sin[idx] = (float)sin((double)ang);
}

// ---------------- pack q_projs/k_projs [h][d][o] -> W[n][d] -----------------
__global__ void prep_wqk_kernel(const float* __restrict__ qp,
                                const float* __restrict__ kp) {
    int n = blockIdx.x;
    const float* src = (n < 256) ? qp : kp;
    int nn = n & 255;
    int h = nn >> 5, o = nn & 31;
    for (int d = threadIdx.x; d < 512; d += blockDim.x)
        g_wqk[n * 512 + d] = src[h * 16384 + d * 32 + o];
}

// ---------------- batched weight conversion (6 matrices) --------------------
__global__ __launch_bounds__(256) void conv_w6_kernel(
    const float* s0, const float* s1, const float* s2,
    const float* s3, const float* s4, const float* s5,
    __nv_bfloat16* d0, __nv_bfloat16* d1, __nv_bfloat16* d2,
    __nv_bfloat16* d3, __nv_bfloat16* d4, __nv_bfloat16* d5) {
    const float* src; __nv_bfloat16* dst;
    switch (blockIdx.y) {
        case 0: src = s0; dst = d0; break;
        case 1: src = s1; dst = d1; break;
        case 2: src = s2; dst = d2; break;
        case 3: src = s3; dst = d3; break;
        case 4: src = s4; dst = d4; break;
        default: src = s5; dst = d5; break;
    }
    int idx = blockIdx.x * 256 + threadIdx.x;
    int row = idx >> 9, col = idx & 511;
    float x = src[idx];
    __nv_bfloat16 h = __float2bfloat16(x);
    __nv_bfloat16 l = __float2bfloat16(x - __bfloat162float(h));
    size_t base = (size_t)row * 1536;
    dst[base + col] = h;
    dst[base + 512 + col] = h;
    dst[base + 1024 + col] = l;
}

// ---------------- activation conversion (x only) ----------------------------
__global__ __launch_bounds__(256) void conv_act_kernel(const float* __restrict__ in,
                                                       __nv_bfloat16* __restrict__ out) {
    int idx = blockIdx.x * 256 + threadIdx.x;
    int row = idx >> 9, col = idx & 511;
    float x = in[idx];
    __nv_bfloat16 h = __float2bfloat16(x);
    __nv_bfloat16 l = __float2bfloat16(x - __bfloat162float(h));
    size_t base = (size_t)row * 1536;
    out[base + col] = h;
    out[base + 512 + col] = l;
    out[base + 1024 + col] = h;
}

// ---------------- HMMA GEMM (double-buffered cp.async) ----------------------
// C[4096][512] = A16[4096][1536] x W16[512][1536]^T ; optional split out S.
// Block 128x64, BK=64, 256 threads, warps 4(m)x2(n), warp tile 32x32.
// epi: 0 none, 1 C=R+acc, 2 C=R+silu(acc)
#define NKT 24
#define STG 24576
__global__ __launch_bounds__(256) void gemm_mma_kernel(
    const __nv_bfloat16* __restrict__ A16, const __nv_bfloat16* __restrict__ W16,
    const float* __restrict__ R, float* __restrict__ C,
    __nv_bfloat16* __restrict__ S, int epi)
{
    __shared__ __align__(128) char sm[2 * STG];
    uint32_t sb = smem_u32(sm);

    int tid = threadIdx.x, wid = tid >> 5, lane = tid & 31;
    int bm = blockIdx.y * 128, bn = blockIdx.x * 64;
    int wm = wid >> 1, wn = wid & 1;

    const __nv_bfloat16* Abase = A16 + (size_t)bm * 1536;
    const __nv_bfloat16* Wbase = W16 + (size_t)bn * 1536;

    auto load_stage = [&](int kt) {
        int buf = kt & 1;
        uint32_t dA = sb + buf * STG;
        uint32_t dB = dA + 16384;
        int kofs = kt * 64;
#pragma unroll
        for (int it = 0; it < 4; it++) {
            int idx = it * 256 + tid, row = idx >> 3, seg = idx & 7;
            uint32_t off = (uint32_t)(row * 128 + ((seg * 16) ^ ((row & 7) << 4)));
            cp16(dA + off, Abase + (size_t)row * 1536 + kofs + seg * 8);
        }
#pragma unroll
        for (int it = 0; it < 2; it++) {
            int idx = it * 256 + tid, row = idx >> 3, seg = idx & 7;
            uint32_t off = (uint32_t)(row * 128 + ((seg * 16) ^ ((row & 7) << 4)));
            cp16(dB + off, Wbase + (size_t)row * 1536 + kofs + seg * 8);
        }
        asm volatile("cp.async.commit_group;" ::: "memory");
    };

    // ldmatrix row/swizzle precompute
    int aRow[2]; uint32_t aSw[2];
#pragma unroll
    for (int mi = 0; mi < 2; mi++) {
        int row = wm * 32 + mi * 16 + (lane & 15);
        aRow[mi] = row;
        aSw[mi] = (uint32_t)((((lane >> 4) << 4)) ^ ((row & 7) << 4));
    }
    int bRow[2]; uint32_t bSw[2];
#pragma unroll
    for (int g = 0; g < 2; g++) {
        int nrow = wn * 32 + g * 16 + (lane & 7) + ((lane >> 4) << 3);
        bRow[g] = nrow;
        bSw[g] = (uint32_t)(((lane & 8) << 1) ^ ((nrow & 7) << 4));
    }

    float c[2][4][4];
#pragma unroll
    for (int mi = 0; mi < 2; mi++)
#pragma unroll
        for (int ni = 0; ni < 4; ni++)
#pragma unroll
            for (int q = 0; q < 4; q++) c[mi][ni][q] = 0.f;

    load_stage(0);

    for (int kt = 0; kt < NKT; kt++) {
        if (kt + 1 < NKT) {
            load_stage(kt + 1);
            asm volatile("cp.async.wait_group 1;" ::: "memory");
        } else {
            asm volatile("cp.async.wait_group 0;" ::: "memory");
        }
        __syncthreads();
        uint32_t base = sb + (uint32_t)(kt & 1) * STG;
        uint32_t baseB = base + 16384;
#pragma unroll
        for (int ks = 0; ks < 4; ks++) {
            uint32_t a0[4], a1[4], b0[4], b1[4];
            ldsm4(a0[0], a0[1], a0[2], a0[3],
                  base + (uint32_t)(aRow[0] * 128) + (uint32_t)((ks * 32) ^ aSw[0]));
            ldsm4(a1[0], a1[1], a1[2], a1[3],
                  base + (uint32_t)(aRow[1] * 128) + (uint32_t)((ks * 32) ^ aSw[1]));
            ldsm4(b0[0], b0[1], b0[2], b0[3],
                  baseB + (uint32_t)(bRow[0] * 128) + (uint32_t)((ks * 32) ^ bSw[0]));
            ldsm4(b1[0], b1[1], b1[2], b1[3],
                  baseB + (uint32_t)(bRow[1] * 128) + (uint32_t)((ks * 32) ^ bSw[1]));
            mma16816(c[0][0][0], c[0][0][1], c[0][0][2], c[0][0][3],
                     a0[0], a0[1], a0[2], a0[3], b0[0], b0[1]);
            mma16816(c[0][1][0], c[0][1][1], c[0][1][2], c[0][1][3],
                     a0[0], a0[1], a0[2], a0[3], b0[2], b0[3]);
            mma16816(c[0][2][0], c[0][2][1], c[0][2][2], c[0][2][3],
                     a0[0], a0[1], a0[2], a0[3], b1[0], b1[1]);
            mma16816(c[0][3][0], c[0][3][1], c[0][3][2], c[0][3][3],
                     a0[0], a0[1], a0[2], a0[3], b1[2], b1[3]);
            mma16816(c[1][0][0], c[1][0][1], c[1][0][2], c[1][0][3],
                     a1[0], a1[1], a1[2], a1[3], b0[0], b0[1]);
            mma16816(c[1][1][0], c[1][1][1], c[1][1][2], c[1][1][3],
                     a1[0], a1[1], a1[2], a1[3], b0[2], b0[3]);
            mma16816(c[1][2][0], c[1][2][1], c[1][2][2], c[1][2][3],
                     a1[0], a1[1], a1[2], a1[3], b1[0], b1[1]);
            mma16816(c[1][3][0], c[1][3][1], c[1][3][2], c[1][3][3],
                     a1[0], a1[1], a1[2], a1[3], b1[2], b1[3]);
        }
        if (kt + 1 < NKT) __syncthreads();
    }

    // ---- epilogue ----
    int gq = lane >> 2, tig = lane & 3;
#pragma unroll
    for (int mi = 0; mi < 2; mi++) {
#pragma unroll
        for (int ni = 0; ni < 4; ni++) {
#pragma unroll
            for (int half = 0; half < 2; half++) {
                int row = bm + wm * 32 + mi * 16 + gq + half * 8;
                int col = bn + wn * 32 + ni * 8 + tig * 2;
                size_t o = (size_t)row * 512 + col;
                float v0 = c[mi][ni][half * 2], v1 = c[mi][ni][half * 2 + 1];
                if (epi == 1) {
                    float2 rr = *(const float2*)(R + o);
                    v0 += rr.x; v1 += rr.y;
                } else if (epi == 2) {
                    float2 rr = *(const float2*)(R + o);
                    v0 = rr.x + v0 / (1.0f + expf(-v0));
                    v1 = rr.y + v1 / (1.0f + expf(-v1));
                }
                if (C) {
                    float2 ov = {v0, v1};
                    *(float2*)(C + o) = ov;
                }
                if (S) {
                    __nv_bfloat16 h0 = __float2bfloat16(v0);
                    __nv_bfloat16 h1 = __float2bfloat16(v1);
                    __nv_bfloat16 l0 = __float2bfloat16(v0 - __bfloat162float(h0));
                    __nv_bfloat16 l1 = __float2bfloat16(v1 - __bfloat162float(h1));
                    size_t sbase = (size_t)row * 1536 + col;
                    __nv_bfloat162 hh; hh.x = h0; hh.y = h1;
                    __nv_bfloat162 ll; ll.x = l0; ll.y = l1;
                    *(__nv_bfloat162*)(S + sbase) = hh;
                    *(__nv_bfloat162*)(S + sbase + 512) = ll;
                    *(__nv_bfloat162*)(S + sbase + 1024) = hh;
                }
            }
        }
    }
}

// ---------------- RoPE + gain + score-scale fold ----------------------------
__global__ __launch_bounds__(256) void rope_kernel(const float* __restrict__ qkraw,
                                                   const float* __restrict__ gain) {
    int token = blockIdx.x;
    int b = token >> 11, t = token & 2047;
    int tid = threadIdx.x;
    int h = tid >> 5, o = tid & 31, i = o & 15;
    float c = g_cos[t * 16 + i];
    float s = g_sin[t * 16 + i];
    const float* row = qkraw + (size_t)token * 512;
    size_t oidx = ((size_t)(b * 8 + h) * T_SEQ + t) * DP + o;

    float q1 = row[h * 32 + i], q2 = row[h * 32 + i + 16];
    float qv = (o < 16) ? (q1 * c - q2 * s) : (q2 * c + q1 * s);
    g_q[oidx] = qv * (gain[h] * 0.17677669529663687f);

    float k1 = row[256 + h * 32 + i], k2 = row[256 + h * 32 + i + 16];
    g_k[oidx] = (o < 16) ? (k1 * c - k2 * s) : (k2 * c + k1 * s);
}

// ---------------- flash attention (f32x2) + self-align, split-bf16 out ------
__global__ __launch_bounds__(128, 1) void attn_kernel(__nv_bfloat16* __restrict__ Y16) {
    __shared__ __align__(16) float ks[128 * 32];
    __shared__ __align__(16) float vs[128 * 64];
    int bh = blockIdx.y, b = bh >> 3, h = bh & 7;
    int tileIdx = (int)gridDim.x - 1 - (int)blockIdx.x;
    int tid = threadIdx.x;
    int r = tileIdx * 128 + tid;

    ull qp[16];
    {
        const ulonglong2* qr = (const ulonglong2*)(g_q + ((size_t)bh * T_SEQ + r) * DP);
#pragma unroll
        for (int i = 0; i < 8; i++) {
            ulonglong2 t2 = qr[i];
            qp[2 * i] = t2.x; qp[2 * i + 1] = t2.y;
        }
    }
    ull accp[32];
#pragma unroll
    for (int d = 0; d < 32; d++) accp[d] = 0ull;
    float mrow = -3.0e38f, l = 0.f;

    int ntiles = tileIdx + 1;
    for (int tile = 0; tile < ntiles; tile++) {
        int j0 = tile * 128;
        {
            const float4* src = (const float4*)(g_k + ((size_t)bh * T_SEQ + j0) * DP);
            float4* dst = (float4*)ks;
#pragma unroll
            for (int i = 0; i < 8; i++) dst[tid + 128 * i] = src[tid + 128 * i];
            float4* vd = (float4*)vs;
#pragma unroll
            for (int i = 0; i < 16; i++) {
                int idx = tid + 128 * i;
                int row = idx >> 4, seg = idx & 15;
                vd[idx] = *(const float4*)(g_v + ((size_t)(b * T_SEQ + j0 + row)) * DM + h * DH + seg * 4);
            }
        }
        __syncthreads();

        for (int jc = 0; jc < 128; jc += 16) {
            float sc[16];
            float cmax = -3.0e38f;
#pragma unroll
            for (int jj = 0; jj < 16; jj++) {
                const ulonglong2* kr = (const ulonglong2*)(ks + (jc + jj) * 32);
                ull s0 = 0ull, s1 = 0ull;
#pragma unroll
                for (int i = 0; i < 8; i++) {
                    ulonglong2 kv = kr[i];
                    s0 = fma2(qp[2 * i], kv.x, s0);
                    s1 = fma2(qp[2 * i + 1], kv.y, s1);
                }
                float2 f0 = unpk(s0), f1 = unpk(s1);
                float s = (f0.x + f0.y) + (f1.x + f1.y);
                s = (j0 + jc + jj <= r) ? s : -3.0e38f;
                sc[jj] = s;
                cmax = fmaxf(cmax, s);
            }
            float mnew = fmaxf(mrow, cmax);
            float corr = __expf(mrow - mnew);
            float psum = 0.f;
#pragma unroll
            for (int jj = 0; jj < 16; jj++) { sc[jj] = __expf(sc[jj] - mnew); psum += sc[jj]; }
            l = l * corr + psum;
            mrow = mnew;
            ull corr2 = dup2(corr);
#pragma unroll
            for (int d = 0; d < 32; d++) accp[d] = mul2(accp[d], corr2);
#pragma unroll
            for (int jj = 0; jj < 16; jj++) {
                ull pj2 = dup2(sc[jj]);
                const ulonglong2* vr = (const ulonglong2*)(vs + (jc + jj) * 64);
#pragma unroll
                for (int d4 = 0; d4 < 16; d4++) {
                    ulonglong2 vv = vr[d4];
                    accp[2 * d4]     = fma2(pj2, vv.x, accp[2 * d4]);
                    accp[2 * d4 + 1] = fma2(pj2, vv.y, accp[2 * d4 + 1]);
                }
            }
        }
        __syncthreads();
    }

    float acc[64];
#pragma unroll
    for (int i = 0; i < 32; i++) {
        float2 f = unpk(accp[i]);
        acc[2 * i] = f.x; acc[2 * i + 1] = f.y;
    }
    float invl = 1.f / l;
#pragma unroll
    for (int d = 0; d < 64; d++) acc[d] *= invl;
    const float* vrow = g_v + ((size_t)(b * T_SEQ + r)) * DM + h * DH;
    float n2 = 0.f;
#pragma unroll
    for (int d4 = 0; d4 < 16; d4++) {
        float4 vv = *(const float4*)(vrow + 4 * d4);
        n2 += vv.x * vv.x + vv.y * vv.y + vv.z * vv.z + vv.w * vv.w;
    }
    float rn = 1.f / fmaxf(sqrtf(n2), 1e-12f);
    float proj = 0.f;
#pragma unroll
    for (int d4 = 0; d4 < 16; d4++) {
        float4 vv = *(const float4*)(vrow + 4 * d4);
        proj += acc[4 * d4] * vv.x + acc[4 * d4 + 1] * vv.y
              + acc[4 * d4 + 2] * vv.z + acc[4 * d4 + 3] * vv.w;
    }
    proj *= rn;
    float prn = proj * rn;

    // write split-bf16 y directly: token row, cols h*64..h*64+63
    size_t sbase = (size_t)(b * T_SEQ + r) * 1536 + h * DH;
#pragma unroll
    for (int d4 = 0; d4 < 16; d4++) {
        float4 vv = *(const float4*)(vrow + 4 * d4);
        float o0 = acc[4 * d4]     - prn * vv.x;
        float o1 = acc[4 * d4 + 1] - prn * vv.y;
        float o2 = acc[4 * d4 + 2] - prn * vv.z;
        float o3 = acc[4 * d4 + 3] - prn * vv.w;
        __nv_bfloat16 h0 = __float2bfloat16(o0), h1 = __float2bfloat16(o1);
        __nv_bfloat16 h2 = __float2bfloat16(o2), h3 = __float2bfloat16(o3);
        __nv_bfloat16 l0 = __float2bfloat16(o0 - __bfloat162float(h0));
        __nv_bfloat16 l1 = __float2bfloat16(o1 - __bfloat162float(h1));
        __nv_bfloat16 l2 = __float2bfloat16(o2 - __bfloat162float(h2));
        __nv_bfloat16 l3 = __float2bfloat16(o3 - __bfloat162float(h3));
        __nv_bfloat162 hA; hA.x = h0; hA.y = h1;
        __nv_bfloat162 hB; hB.x = h2; hB.y = h3;
        __nv_bfloat162 lA; lA.x = l0; lA.y = l1;
        __nv_bfloat162 lB; lB.x = l2; lB.y = l3;
        size_t p = sbase + 4 * d4;
        *(__nv_bfloat162*)(Y16 + p) = hA;
        *(__nv_bfloat162*)(Y16 + p + 2) = hB;
        *(__nv_bfloat162*)(Y16 + p + 512) = lA;
        *(__nv_bfloat162*)(Y16 + p + 514) = lB;
        *(__nv_bfloat162*)(Y16 + p + 1024) = hA;
        *(__nv_bfloat162*)(Y16 + p + 1026) = hB;
    }
}

// ---------------- layernorm with split-bf16 output --------------------------
__global__ __launch_bounds__(256) void ln_split_kernel(const float* __restrict__ in,
                                                       const float* __restrict__ g,
                                                       const float* __restrict__ b,
                                                       __nv_bfloat16* __restrict__ S) {
    int row = blockIdx.x, tid = threadIdx.x;
    const float* rp = in + (size_t)row * 512;
    float a0 = rp[tid], a1 = rp[tid + 256];
    float s = a0 + a1, s2 = a0 * a0 + a1 * a1;
#pragma unroll
    for (int off = 16; off; off >>= 1) {
        s  += __shfl_down_sync(0xffffffffu, s, off);
        s2 += __shfl_down_sync(0xffffffffu, s2, off);
    }
    __shared__ float rs[8], rs2[8];
    __shared__ float mean_s, inv_s;
    if ((tid & 31) == 0) { rs[tid >> 5] = s; rs2[tid >> 5] = s2; }
    __syncthreads();
    if (tid == 0) {
        float S0 = 0, S2 = 0;
#pragma unroll
        for (int w = 0; w < 8; w++) { S0 += rs[w]; S2 += rs2[w]; }
        float m = S0 * (1.0f / 512.0f);
        float var = fmaxf(S2 * (1.0f / 512.0f) - m * m, 0.0f);
        mean_s = m;
        inv_s = rsqrtf(var + 1e-5f);
    }
    __syncthreads();
    float v0 = (a0 - mean_s) * inv_s * g[tid] + b[tid];
    float v1 = (a1 - mean_s) * inv_s * g[tid + 256] + b[tid + 256];
    size_t base = (size_t)row * 1536;
    __nv_bfloat16 h0 = __float2bfloat16(v0);
    __nv_bfloat16 l0 = __float2bfloat16(v0 - __bfloat162float(h0));
    __nv_bfloat16 h1 = __float2bfloat16(v1);
    __nv_bfloat16 l1 = __float2bfloat16(v1 - __bfloat162float(h1));
    S[base + tid] = h0;       S[base + 512 + tid] = l0;       S[base + 1024 + tid] = h0;
    S[base + tid + 256] = h1; S[base + 512 + tid + 256] = l1; S[base + 1024 + tid + 256] = h1;
}

// ---------------- rms norm --------------------------------------------------
__global__ __launch_bounds__(256) void rms_kernel(const float* __restrict__ in,
                                                  float* __restrict__ out) {
    int row = blockIdx.x, tid = threadIdx.x;
    const float* rp = in + (size_t)row * 512;
    float a0 = rp[tid], a1 = rp[tid + 256];
    float s2 = a0 * a0 + a1 * a1;
#pragma unroll
    for (int off = 16; off; off >>= 1) s2 += __shfl_down_sync(0xffffffffu, s2, off);
    __shared__ float rs2[8];
    __shared__ float inv_s;
    if ((tid & 31) == 0) rs2[tid >> 5] = s2;
    __syncthreads();
    if (tid == 0) {
        float S2 = 0;
#pragma unroll
        for (int w = 0; w < 8; w++) S2 += rs2[w];
        inv_s = rsqrtf(S2 * (1.0f / 512.0f) + 1e-6f);
    }
    __syncthreads();
    out[(size_t)row * 512 + tid]       = a0 * inv_s;
    out[(size_t)row * 512 + tid + 256] = a1 * inv_s;
}

// ---------------- final projection + tanh(coord temp) -----------------------
__global__ __launch_bounds__(256) void zout_kernel(const float* __restrict__ hrms,
                                                   const float* __restrict__ wout,
                                                   const float* __restrict__ ct,
                                                   float* __restrict__ z) {
    int token = blockIdx.x, tid = threadIdx.x;
    __shared__ float xs[512];
    __shared__ float ps[256];
    const float* rp = hrms + (size_t)token * 512;
    xs[tid] = rp[tid];
    xs[tid + 256] = rp[tid + 256];
    __syncthreads();
    int n = tid & 31, g = tid >> 5;
    const float* wr = wout + n * 512 + g * 64;
    const float* xr = xs + g * 64;
    float p = 0.f;
#pragma unroll
    for (int d = 0; d < 64; d++) p += xr[d] * wr[d];
    ps[tid] = p;
    __syncthreads();
    if (tid < 32) {
        float s = 0.f;
#pragma unroll
        for (int gg = 0; gg < 8; gg++) s += ps[gg * 32 + tid];
        float c = ct[tid];
        float sp = log1pf(expf(c));
        z[(size_t)token * 32 + tid] = tanhf(s / (sp + 1e-4f));
    }
}

// ---------------- host ------------------------------------------------------
static float* sym_addr_f(const void* symbol) {
    void* p = nullptr;
    cudaGetSymbolAddress(&p, symbol);
    return (float*)p;
}
static __nv_bfloat16* sym_addr_b(const void* symbol) {
    void* p = nullptr;
    cudaGetSymbolAddress(&p, symbol);
    return (__nv_bfloat16*)p;
}

extern "C" void kernel_launch(void* const* d_in, const int* in_sizes, int n_in,
                              void* d_out, int out_size) {
    const float* x     = (const float*)d_in[0];
    const float* qp    = (const float*)d_in[1];
    const float* kp    = (const float*)d_in[2];
    const float* wv    = (const float*)d_in[3];
    const float* wproj = (const float*)d_in[4];
    const float* qgain = (const float*)d_in[5];
    const float* ew0   = (const float*)d_in[6];
    const float* g1    = (const float*)d_in[7];
    const float* b1    = (const float*)d_in[8];
    const float* ew1   = (const float*)d_in[9];
    const float* g2    = (const float*)d_in[10];
    const float* b2    = (const float*)d_in[11];
    const float* ew2   = (const float*)d_in[12];
    const float* ewout = (const float*)d_in[13];
    const float* ct    = (const float*)d_in[14];
    float* z = (float*)d_out;

    float* wqk   = sym_addr_f(g_wqk);
    float* qkraw = sym_addr_f(g_qkraw);
    float* v     = sym_addr_f(g_v);
    float* h     = sym_addr_f(g_h);
    float* he0   = sym_addr_f(g_he0);
    float* he1   = sym_addr_f(g_he1);
    float* he2   = sym_addr_f(g_he2);
    float* hrms  = sym_addr_f(g_hrms);

    __nv_bfloat16* a16   = sym_addr_b(g_a16);
    __nv_bfloat16* b16   = sym_addr_b(g_b16);
    __nv_bfloat16* wqk16 = sym_addr_b(g_w16qk);
    __nv_bfloat16* wv16  = sym_addr_b(g_w16v);
    __nv_bfloat16* wp16  = sym_addr_b(g_w16p);
    __nv_bfloat16* we016 = sym_addr_b(g_w16e0);
    __nv_bfloat16* we116 = sym_addr_b(g_w16e1);
    __nv_bfloat16* we216 = sym_addr_b(g_w16e2);

    dim3 ggrid(8, 32);   // N/64 = 8, M/128 = 32
    const int WBLK = 512 * 512 / 256;
    const int ABLK = NTOK * 512 / 256;

    // launch order arranged so slot 5 (ncu -s 5 -c 1) captures gemm_mma_kernel
    trig_table_kernel<<<256, 128>>>();                                      // 0
    prep_wqk_kernel<<<512, 256>>>(qp, kp);                                  // 1
    conv_w6_kernel<<<dim3(WBLK, 6), 256>>>(wqk, wv, wproj, ew0, ew1, ew2,   // 2
                                           wqk16, wv16, wp16, we016, we116, we216);
    conv_act_kernel<<<ABLK, 256>>>(x, a16);                                 // 3
    gemm_mma_kernel<<<ggrid, 256>>>(a16, wqk16, nullptr, qkraw, nullptr, 0);// 4
    gemm_mma_kernel<<<ggrid, 256>>>(a16, wv16, nullptr, v, nullptr, 0);     // 5 <- profiled
    rope_kernel<<<4096, 256>>>(qkraw, qgain);                               // 6
    attn_kernel<<<dim3(16, 16), 128>>>(b16);                                // 7
    gemm_mma_kernel<<<ggrid, 256>>>(b16, wp16, x, h, a16, 1);               // 8
    gemm_mma_kernel<<<ggrid, 256>>>(a16, we016, nullptr, he0, nullptr, 0);  // 9
    ln_split_kernel<<<4096, 256>>>(he0, g1, b1, b16);                       // 10
    gemm_mma_kernel<<<ggrid, 256>>>(b16, we116, h, he1, nullptr, 2);        // 11
    ln_split_kernel<<<4096, 256>>>(he1, g2, b2, a16);                       // 12
    gemm_mma_kernel<<<ggrid, 256>>>(a16, we216, he1, he2, nullptr, 2);      // 13
    rms_kernel<<<4096, 256>>>(he2, hrms);                                   // 14
    zout_kernel<<<4096, 256>>>(hrms, ewout, ct, z);                         // 15
}

// round 6
// speedup vs baseline: 1.4219x; 1.0096x over previous
#include <cuda_runtime.h>
#include <cuda_bf16.h>
#include <math.h>
#include <stdint.h>

#define T_SEQ 2048
#define NTOK  4096
#define DM    512
#define NH    8
#define DH    64
#define DP    32

typedef unsigned long long ull;

// ---------------- f32x2 packed helpers --------------------------------------
__device__ __forceinline__ ull fma2(ull a, ull b, ull c) {
    ull d; asm("fma.rn.f32x2 %0,%1,%2,%3;" : "=l"(d) : "l"(a), "l"(b), "l"(c));
    return d;
}
__device__ __forceinline__ ull mul2(ull a, ull b) {
    ull d; asm("mul.rn.f32x2 %0,%1,%2;" : "=l"(d) : "l"(a), "l"(b));
    return d;
}
__device__ __forceinline__ ull dup2(float a) {
    ull d; asm("mov.b64 %0,{%1,%1};" : "=l"(d) : "f"(a));
    return d;
}
__device__ __forceinline__ float2 unpk(ull a) {
    float2 f; asm("mov.b64 {%0,%1},%2;" : "=f"(f.x), "=f"(f.y) : "l"(a));
    return f;
}

// ---------------- mma / async helpers ----------------------------------------
__device__ __forceinline__ uint32_t smem_u32(const void* p) {
    uint32_t a;
    asm("{ .reg .u64 t; cvta.to.shared.u64 t, %1; cvt.u32.u64 %0, t; }"
        : "=r"(a) : "l"(p));
    return a;
}
__device__ __forceinline__ void cp16(uint32_t dst, const void* src) {
    asm volatile("cp.async.cg.shared.global [%0], [%1], 16;"
        :: "r"(dst), "l"(src) : "memory");
}
__device__ __forceinline__ void ldsm4(uint32_t& r0, uint32_t& r1, uint32_t& r2,
                                      uint32_t& r3, uint32_t addr) {
    asm volatile("ldmatrix.sync.aligned.m8n8.x4.shared.b16 {%0,%1,%2,%3}, [%4];"
        : "=r"(r0), "=r"(r1), "=r"(r2), "=r"(r3) : "r"(addr));
}
__device__ __forceinline__ void mma16816(float& c0, float& c1, float& c2, float& c3,
                                         uint32_t a0, uint32_t a1, uint32_t a2,
                                         uint32_t a3, uint32_t b0, uint32_t b1) {
    asm volatile("mma.sync.aligned.m16n8k16.row.col.f32.bf16.bf16.f32 "
        "{%0,%1,%2,%3}, {%4,%5,%6,%7}, {%8,%9}, {%0,%1,%2,%3};"
        : "+f"(c0), "+f"(c1), "+f"(c2), "+f"(c3)
        : "r"(a0), "r"(a1), "r"(a2), "r"(a3), "r"(b0), "r"(b1));
}

// ---------------- scratch (device globals) ----------------------------------
__device__ __align__(16) float g_wqk[512 * 512];
__device__ __align__(16) float g_qkraw[NTOK * 512];
__device__ __align__(16) float g_q[16 * T_SEQ * DP];
__device__ __align__(16) float g_k[16 * T_SEQ * DP];
__device__ __align__(16) float g_v[NTOK * DM];
__device__ __align__(16) float g_h[NTOK * DM];
__device__ __align__(16) float g_he0[NTOK * DM];
__device__ __align__(16) float g_he1[NTOK * DM];
__device__ __align__(16) float g_he2[NTOK * DM];
__device__ __align__(16) float g_hrms[NTOK * DM];
__device__ __align__(16) float g_cos[T_SEQ * 16];
__device__ __align__(16) float g_sin[T_SEQ * 16];

// activation split buffers (A/B ping-pong): [4096][1536] = [hi|lo|hi]
__device__ __align__(16) __nv_bfloat16 g_a16[NTOK * 1536];
__device__ __align__(16) __nv_bfloat16 g_b16[NTOK * 1536];
// weight split buffers: [512][1536] = [hi|hi|lo]
__device__ __align__(16) __nv_bfloat16 g_w16qk[512 * 1536];
__device__ __align__(16) __nv_bfloat16 g_w16v[512 * 1536];
__device__ __align__(16) __nv_bfloat16 g_w16p[512 * 1536];
__device__ __align__(16) __nv_bfloat16 g_w16e0[512 * 1536];
__device__ __align__(16) __nv_bfloat16 g_w16e1[512 * 1536];
__device__ __align__(16) __nv_bfloat16 g_w16e2[512 * 1536];

// ---------------- RoPE trig table -------------------------------------------
__global__ void trig_table_kernel() {
    int idx = blockIdx.x * blockDim.x + threadIdx.x;
    if (idx >= T_SEQ * 16) return;
    int t = idx >> 4, i = idx & 15;
    double p = pow(10000.0, (double)i / 16.0);
    float pf = (float)p;
    float freq = 1.0f / pf;
    float ang = (float)t * freq;
    g_cos[idx] = (float)cos((double)ang);
    g_sin[idx] = (float)sin((double)ang);
}

// ---------------- pack q_projs/k_projs [h][d][o] -> W[n][d] -----------------
__global__ void prep_wqk_kernel(const float* __restrict__ qp,
                                const float* __restrict__ kp) {
    int n = blockIdx.x;
    const float* src = (n < 256) ? qp : kp;
    int nn = n & 255;
    int h = nn >> 5, o = nn & 31;
    for (int d = threadIdx.x; d < 512; d += blockDim.x)
        g_wqk[n * 512 + d] = src[h * 16384 + d * 32 + o];
}

// ---------------- weight conversion: single ---------------------------------
__global__ __launch_bounds__(256) void conv_w_kernel(const float* __restrict__ in,
                                                     __nv_bfloat16* __restrict__ out) {
    int idx = blockIdx.x * 256 + threadIdx.x;
    int row = idx >> 9, col = idx & 511;
    float x = in[idx];
    __nv_bfloat16 h = __float2bfloat16(x);
    __nv_bfloat16 l = __float2bfloat16(x - __bfloat162float(h));
    size_t base = (size_t)row * 1536;
    out[base + col] = h;
    out[base + 512 + col] = h;
    out[base + 1024 + col] = l;
}

// ---------------- weight conversion: batched 5 -------------------------------
__global__ __launch_bounds__(256) void conv_w5_kernel(
    const float* s0, const float* s1, const float* s2,
    const float* s3, const float* s4,
    __nv_bfloat16* d0, __nv_bfloat16* d1, __nv_bfloat16* d2,
    __nv_bfloat16* d3, __nv_bfloat16* d4) {
    const float* src; __nv_bfloat16* dst;
    switch (blockIdx.y) {
        case 0: src = s0; dst = d0; break;
        case 1: src = s1; dst = d1; break;
        case 2: src = s2; dst = d2; break;
        case 3: src = s3; dst = d3; break;
        default: src = s4; dst = d4; break;
    }
    int idx = blockIdx.x * 256 + threadIdx.x;
    int row = idx >> 9, col = idx & 511;
    float x = src[idx];
    __nv_bfloat16 h = __float2bfloat16(x);
    __nv_bfloat16 l = __float2bfloat16(x - __bfloat162float(h));
    size_t base = (size_t)row * 1536;
    dst[base + col] = h;
    dst[base + 512 + col] = h;
    dst[base + 1024 + col] = l;
}

// ---------------- activation conversion (x only) ----------------------------
__global__ __launch_bounds__(256) void conv_act_kernel(const float* __restrict__ in,
                                                       __nv_bfloat16* __restrict__ out) {
    int idx = blockIdx.x * 256 + threadIdx.x;
    int row = idx >> 9, col = idx & 511;
    float x = in[idx];
    __nv_bfloat16 h = __float2bfloat16(x);
    __nv_bfloat16 l = __float2bfloat16(x - __bfloat162float(h));
    size_t base = (size_t)row * 1536;
    out[base + col] = h;
    out[base + 512 + col] = l;
    out[base + 1024 + col] = h;
}

// ---------------- HMMA GEMM (128x128 tile, double-buffered cp.async) --------
// C[4096][512] = A16[4096][1536] x W16[512][1536]^T ; optional split out S.
// Block 128x128, BK=64, 256 threads, warps 4(m)x2(n), warp tile 32x64.
// epi: 0 none, 1 C=R+acc, 2 C=R+silu(acc)
#define NKT 24
#define STG 32768
#define GSMEM (2 * STG)
__global__ __launch_bounds__(256) void gemm_mma_kernel(
    const __nv_bfloat16* __restrict__ A16, const __nv_bfloat16* __restrict__ W16,
    const float* __restrict__ R, float* __restrict__ C,
    __nv_bfloat16* __restrict__ S, int epi)
{
    extern __shared__ __align__(128) char sm[];
    uint32_t sb = smem_u32(sm);

    int tid = threadIdx.x, wid = tid >> 5, lane = tid & 31;
    int bm = blockIdx.y * 128, bn = blockIdx.x * 128;
    int wm = wid >> 1, wn = wid & 1;

    const __nv_bfloat16* Abase = A16 + (size_t)bm * 1536;
    const __nv_bfloat16* Wbase = W16 + (size_t)bn * 1536;

    auto load_stage = [&](int kt) {
        uint32_t dA = sb + (uint32_t)(kt & 1) * STG;
        uint32_t dB = dA + 16384;
        int kofs = kt * 64;
#pragma unroll
        for (int it = 0; it < 4; it++) {
            int idx = it * 256 + tid, row = idx >> 3, seg = idx & 7;
            uint32_t off = (uint32_t)(row * 128 + ((seg * 16) ^ ((row & 7) << 4)));
            cp16(dA + off, Abase + (size_t)row * 1536 + kofs + seg * 8);
        }
#pragma unroll
        for (int it = 0; it < 4; it++) {
            int idx = it * 256 + tid, row = idx >> 3, seg = idx & 7;
            uint32_t off = (uint32_t)(row * 128 + ((seg * 16) ^ ((row & 7) << 4)));
            cp16(dB + off, Wbase + (size_t)row * 1536 + kofs + seg * 8);
        }
        asm volatile("cp.async.commit_group;" ::: "memory");
    };

    // ldmatrix row/swizzle precompute
    int aRow[2]; uint32_t aSw[2];
#pragma unroll
    for (int mi = 0; mi < 2; mi++) {
        int row = wm * 32 + mi * 16 + (lane & 15);
        aRow[mi] = row;
        aSw[mi] = (uint32_t)((((lane >> 4) << 4)) ^ ((row & 7) << 4));
    }
    int bRow[4]; uint32_t bSw[4];
#pragma unroll
    for (int g = 0; g < 4; g++) {
        int nrow = wn * 64 + g * 16 + (lane & 7) + ((lane >> 4) << 3);
        bRow[g] = nrow;
        bSw[g] = (uint32_t)(((lane & 8) << 1) ^ ((nrow & 7) << 4));
    }

    float c[2][8][4];
#pragma unroll
    for (int mi = 0; mi < 2; mi++)
#pragma unroll
        for (int ni = 0; ni < 8; ni++)
#pragma unroll
            for (int q = 0; q < 4; q++) c[mi][ni][q] = 0.f;

    load_stage(0);

    for (int kt = 0; kt < NKT; kt++) {
        if (kt + 1 < NKT) {
            load_stage(kt + 1);
            asm volatile("cp.async.wait_group 1;" ::: "memory");
        } else {
            asm volatile("cp.async.wait_group 0;" ::: "memory");
        }
        __syncthreads();
        uint32_t base = sb + (uint32_t)(kt & 1) * STG;
        uint32_t baseB = base + 16384;
#pragma unroll
        for (int ks = 0; ks < 4; ks++) {
            uint32_t a0[4], a1[4], b[4][4];
            ldsm4(a0[0], a0[1], a0[2], a0[3],
                  base + (uint32_t)(aRow[0] * 128) + (uint32_t)((ks * 32) ^ aSw[0]));
            ldsm4(a1[0], a1[1], a1[2], a1[3],
                  base + (uint32_t)(aRow[1] * 128) + (uint32_t)((ks * 32) ^ aSw[1]));
#pragma unroll
            for (int g = 0; g < 4; g++)
                ldsm4(b[g][0], b[g][1], b[g][2], b[g][3],
                      baseB + (uint32_t)(bRow[g] * 128) + (uint32_t)((ks * 32) ^ bSw[g]));
#pragma unroll
            for (int g = 0; g < 4; g++) {
                mma16816(c[0][2 * g][0], c[0][2 * g][1], c[0][2 * g][2], c[0][2 * g][3],
                         a0[0], a0[1], a0[2], a0[3], b[g][0], b[g][1]);
                mma16816(c[0][2 * g + 1][0], c[0][2 * g + 1][1], c[0][2 * g + 1][2], c[0][2 * g + 1][3],
                         a0[0], a0[1], a0[2], a0[3], b[g][2], b[g][3]);
                mma16816(c[1][2 * g][0], c[1][2 * g][1], c[1][2 * g][2], c[1][2 * g][3],
                         a1[0], a1[1], a1[2], a1[3], b[g][0], b[g][1]);
                mma16816(c[1][2 * g + 1][0], c[1][2 * g + 1][1], c[1][2 * g + 1][2], c[1][2 * g + 1][3],
                         a1[0], a1[1], a1[2], a1[3], b[g][2], b[g][3]);
            }
        }
        if (kt + 1 < NKT) __syncthreads();
    }

    // ---- epilogue ----
    int gq = lane >> 2, tig = lane & 3;
#pragma unroll
    for (int mi = 0; mi < 2; mi++) {
#pragma unroll
        for (int ni = 0; ni < 8; ni++) {
#pragma unroll
            for (int half = 0; half < 2; half++) {
                int row = bm + wm * 32 + mi * 16 + gq + half * 8;
                int col = bn + wn * 64 + ni * 8 + tig * 2;
                size_t o = (size_t)row * 512 + col;
                float v0 = c[mi][ni][half * 2], v1 = c[mi][ni][half * 2 + 1];
                if (epi == 1) {
                    float2 rr = *(const float2*)(R + o);
                    v0 += rr.x; v1 += rr.y;
                } else if (epi == 2) {
                    float2 rr = *(const float2*)(R + o);
                    v0 = rr.x + v0 / (1.0f + expf(-v0));
                    v1 = rr.y + v1 / (1.0f + expf(-v1));
                }
                if (C) {
                    float2 ov = {v0, v1};
                    *(float2*)(C + o) = ov;
                }
                if (S) {
                    __nv_bfloat16 h0 = __float2bfloat16(v0);
                    __nv_bfloat16 h1 = __float2bfloat16(v1);
                    __nv_bfloat16 l0 = __float2bfloat16(v0 - __bfloat162float(h0));
                    __nv_bfloat16 l1 = __float2bfloat16(v1 - __bfloat162float(h1));
                    size_t sbase = (size_t)row * 1536 + col;
                    __nv_bfloat162 hh; hh.x = h0; hh.y = h1;
                    __nv_bfloat162 ll; ll.x = l0; ll.y = l1;
                    *(__nv_bfloat162*)(S + sbase) = hh;
                    *(__nv_bfloat162*)(S + sbase + 512) = ll;
                    *(__nv_bfloat162*)(S + sbase + 1024) = hh;
                }
            }
        }
    }
}

// ---------------- RoPE + gain + score-scale fold ----------------------------
__global__ __launch_bounds__(256) void rope_kernel(const float* __restrict__ qkraw,
                                                   const float* __restrict__ gain) {
    int token = blockIdx.x;
    int b = token >> 11, t = token & 2047;
    int tid = threadIdx.x;
    int h = tid >> 5, o = tid & 31, i = o & 15;
    float c = g_cos[t * 16 + i];
    float s = g_sin[t * 16 + i];
    const float* row = qkraw + (size_t)token * 512;
    size_t oidx = ((size_t)(b * 8 + h) * T_SEQ + t) * DP + o;

    float q1 = row[h * 32 + i], q2 = row[h * 32 + i + 16];
    float qv = (o < 16) ? (q1 * c - q2 * s) : (q2 * c + q1 * s);
    g_q[oidx] = qv * (gain[h] * 0.17677669529663687f);

    float k1 = row[256 + h * 32 + i], k2 = row[256 + h * 32 + i + 16];
    g_k[oidx] = (o < 16) ? (k1 * c - k2 * s) : (k2 * c + k1 * s);
}

// ---------------- flash attention (f32x2) + self-align, split-bf16 out ------
__global__ __launch_bounds__(128, 1) void attn_kernel(__nv_bfloat16* __restrict__ Y16) {
    __shared__ __align__(16) float ks[128 * 32];
    __shared__ __align__(16) float vs[128 * 64];
    int bh = blockIdx.y, b = bh >> 3, h = bh & 7;
    int tileIdx = (int)gridDim.x - 1 - (int)blockIdx.x;
    int tid = threadIdx.x;
    int r = tileIdx * 128 + tid;

    ull qp[16];
    {
        const ulonglong2* qr = (const ulonglong2*)(g_q + ((size_t)bh * T_SEQ + r) * DP);
#pragma unroll
        for (int i = 0; i < 8; i++) {
            ulonglong2 t2 = qr[i];
            qp[2 * i] = t2.x; qp[2 * i + 1] = t2.y;
        }
    }
    ull accp[32];
#pragma unroll
    for (int d = 0; d < 32; d++) accp[d] = 0ull;
    float mrow = -3.0e38f, l = 0.f;

    int ntiles = tileIdx + 1;
    for (int tile = 0; tile < ntiles; tile++) {
        int j0 = tile * 128;
        {
            const float4* src = (const float4*)(g_k + ((size_t)bh * T_SEQ + j0) * DP);
            float4* dst = (float4*)ks;
#pragma unroll
            for (int i = 0; i < 8; i++) dst[tid + 128 * i] = src[tid + 128 * i];
            float4* vd = (float4*)vs;
#pragma unroll
            for (int i = 0; i < 16; i++) {
                int idx = tid + 128 * i;
                int row = idx >> 4, seg = idx & 15;
                vd[idx] = *(const float4*)(g_v + ((size_t)(b * T_SEQ + j0 + row)) * DM + h * DH + seg * 4);
            }
        }
        __syncthreads();

        for (int jc = 0; jc < 128; jc += 16) {
            float sc[16];
            float cmax = -3.0e38f;
#pragma unroll
            for (int jj = 0; jj < 16; jj++) {
                const ulonglong2* kr = (const ulonglong2*)(ks + (jc + jj) * 32);
                ull s0 = 0ull, s1 = 0ull;
#pragma unroll
                for (int i = 0; i < 8; i++) {
                    ulonglong2 kv = kr[i];
                    s0 = fma2(qp[2 * i], kv.x, s0);
                    s1 = fma2(qp[2 * i + 1], kv.y, s1);
                }
                float2 f0 = unpk(s0), f1 = unpk(s1);
                float s = (f0.x + f0.y) + (f1.x + f1.y);
                s = (j0 + jc + jj <= r) ? s : -3.0e38f;
                sc[jj] = s;
                cmax = fmaxf(cmax, s);
            }
            float mnew = fmaxf(mrow, cmax);
            float corr = __expf(mrow - mnew);
            float psum = 0.f;
#pragma unroll
            for (int jj = 0; jj < 16; jj++) { sc[jj] = __expf(sc[jj] - mnew); psum += sc[jj]; }
            l = l * corr + psum;
            mrow = mnew;
            ull corr2 = dup2(corr);
#pragma unroll
            for (int d = 0; d < 32; d++) accp[d] = mul2(accp[d], corr2);
#pragma unroll
            for (int jj = 0; jj < 16; jj++) {
                ull pj2 = dup2(sc[jj]);
                const ulonglong2* vr = (const ulonglong2*)(vs + (jc + jj) * 64);
#pragma unroll
                for (int d4 = 0; d4 < 16; d4++) {
                    ulonglong2 vv = vr[d4];
                    accp[2 * d4]     = fma2(pj2, vv.x, accp[2 * d4]);
                    accp[2 * d4 + 1] = fma2(pj2, vv.y, accp[2 * d4 + 1]);
                }
            }
        }
        __syncthreads();
    }

    float acc[64];
#pragma unroll
    for (int i = 0; i < 32; i++) {
        float2 f = unpk(accp[i]);
        acc[2 * i] = f.x; acc[2 * i + 1] = f.y;
    }
    float invl = 1.f / l;
#pragma unroll
    for (int d = 0; d < 64; d++) acc[d] *= invl;
    const float* vrow = g_v + ((size_t)(b * T_SEQ + r)) * DM + h * DH;
    float n2 = 0.f;
#pragma unroll
    for (int d4 = 0; d4 < 16; d4++) {
        float4 vv = *(const float4*)(vrow + 4 * d4);
        n2 += vv.x * vv.x + vv.y * vv.y + vv.z * vv.z + vv.w * vv.w;
    }
    float rn = 1.f / fmaxf(sqrtf(n2), 1e-12f);
    float proj = 0.f;
#pragma unroll
    for (int d4 = 0; d4 < 16; d4++) {
        float4 vv = *(const float4*)(vrow + 4 * d4);
        proj += acc[4 * d4] * vv.x + acc[4 * d4 + 1] * vv.y
              + acc[4 * d4 + 2] * vv.z + acc[4 * d4 + 3] * vv.w;
    }
    proj *= rn;
    float prn = proj * rn;

    size_t sbase = (size_t)(b * T_SEQ + r) * 1536 + h * DH;
#pragma unroll
    for (int d4 = 0; d4 < 16; d4++) {
        float4 vv = *(const float4*)(vrow + 4 * d4);
        float o0 = acc[4 * d4]     - prn * vv.x;
        float o1 = acc[4 * d4 + 1] - prn * vv.y;
        float o2 = acc[4 * d4 + 2] - prn * vv.z;
        float o3 = acc[4 * d4 + 3] - prn * vv.w;
        __nv_bfloat16 h0 = __float2bfloat16(o0), h1 = __float2bfloat16(o1);
        __nv_bfloat16 h2 = __float2bfloat16(o2), h3 = __float2bfloat16(o3);
        __nv_bfloat16 l0 = __float2bfloat16(o0 - __bfloat162float(h0));
        __nv_bfloat16 l1 = __float2bfloat16(o1 - __bfloat162float(h1));
        __nv_bfloat16 l2 = __float2bfloat16(o2 - __bfloat162float(h2));
        __nv_bfloat16 l3 = __float2bfloat16(o3 - __bfloat162float(h3));
        __nv_bfloat162 hA; hA.x = h0; hA.y = h1;
        __nv_bfloat162 hB; hB.x = h2; hB.y = h3;
        __nv_bfloat162 lA; lA.x = l0; lA.y = l1;
        __nv_bfloat162 lB; lB.x = l2; lB.y = l3;
        size_t p = sbase + 4 * d4;
        *(__nv_bfloat162*)(Y16 + p) = hA;
        *(__nv_bfloat162*)(Y16 + p + 2) = hB;
        *(__nv_bfloat162*)(Y16 + p + 512) = lA;
        *(__nv_bfloat162*)(Y16 + p + 514) = lB;
        *(__nv_bfloat162*)(Y16 + p + 1024) = hA;
        *(__nv_bfloat162*)(Y16 + p + 1026) = hB;
    }
}

// ---------------- layernorm with split-bf16 output --------------------------
__global__ __launch_bounds__(256) void ln_split_kernel(const float* __restrict__ in,
                                                       const float* __restrict__ g,
                                                       const float* __restrict__ b,
                                                       __nv_bfloat16* __restrict__ S) {
    int row = blockIdx.x, tid = threadIdx.x;
    const float* rp = in + (size_t)row * 512;
    float a0 = rp[tid], a1 = rp[tid + 256];
    float s = a0 + a1, s2 = a0 * a0 + a1 * a1;
#pragma unroll
    for (int off = 16; off; off >>= 1) {
        s  += __shfl_down_sync(0xffffffffu, s, off);
        s2 += __shfl_down_sync(0xffffffffu, s2, off);
    }
    __shared__ float rs[8], rs2[8];
    __shared__ float mean_s, inv_s;
    if ((tid & 31) == 0) { rs[tid >> 5] = s; rs2[tid >> 5] = s2; }
    __syncthreads();
    if (tid == 0) {
        float S0 = 0, S2 = 0;
#pragma unroll
        for (int w = 0; w < 8; w++) { S0 += rs[w]; S2 += rs2[w]; }
        float m = S0 * (1.0f / 512.0f);
        float var = fmaxf(S2 * (1.0f / 512.0f) - m * m, 0.0f);
        mean_s = m;
        inv_s = rsqrtf(var + 1e-5f);
    }
    __syncthreads();
    float v0 = (a0 - mean_s) * inv_s * g[tid] + b[tid];
    float v1 = (a1 - mean_s) * inv_s * g[tid + 256] + b[tid + 256];
    size_t base = (size_t)row * 1536;
    __nv_bfloat16 h0 = __float2bfloat16(v0);
    __nv_bfloat16 l0 = __float2bfloat16(v0 - __bfloat162float(h0));
    __nv_bfloat16 h1 = __float2bfloat16(v1);
    __nv_bfloat16 l1 = __float2bfloat16(v1 - __bfloat162float(h1));
    S[base + tid] = h0;       S[base + 512 + tid] = l0;       S[base + 1024 + tid] = h0;
    S[base + tid + 256] = h1; S[base + 512 + tid + 256] = l1; S[base + 1024 + tid + 256] = h1;
}

// ---------------- rms norm --------------------------------------------------
__global__ __launch_bounds__(256) void rms_kernel(const float* __restrict__ in,
                                                  float* __restrict__ out) {
    int row = blockIdx.x, tid = threadIdx.x;
    const float* rp = in + (size_t)row * 512;
    float a0 = rp[tid], a1 = rp[tid + 256];
    float s2 = a0 * a0 + a1 * a1;
#pragma unroll
    for (int off = 16; off; off >>= 1) s2 += __shfl_down_sync(0xffffffffu, s2, off);
    __shared__ float rs2[8];
    __shared__ float inv_s;
    if ((tid & 31) == 0) rs2[tid >> 5] = s2;
    __syncthreads();
    if (tid == 0) {
        float S2 = 0;
#pragma unroll
        for (int w = 0; w < 8; w++) S2 += rs2[w];
        inv_s = rsqrtf(S2 * (1.0f / 512.0f) + 1e-6f);
    }
    __syncthreads();
    out[(size_t)row * 512 + tid]       = a0 * inv_s;
    out[(size_t)row * 512 + tid + 256] = a1 * inv_s;
}

// ---------------- final projection + tanh(coord temp) -----------------------
__global__ __launch_bounds__(256) void zout_kernel(const float* __restrict__ hrms,
                                                   const float* __restrict__ wout,
                                                   const float* __restrict__ ct,
                                                   float* __restrict__ z) {
    int token = blockIdx.x, tid = threadIdx.x;
    __shared__ float xs[512];
    __shared__ float ps[256];
    const float* rp = hrms + (size_t)token * 512;
    xs[tid] = rp[tid];
    xs[tid + 256] = rp[tid + 256];
    __syncthreads();
    int n = tid & 31, g = tid >> 5;
    const float* wr = wout + n * 512 + g * 64;
    const float* xr = xs + g * 64;
    float p = 0.f;
#pragma unroll
    for (int d = 0; d < 64; d++) p += xr[d] * wr[d];
    ps[tid] = p;
    __syncthreads();
    if (tid < 32) {
        float s = 0.f;
#pragma unroll
        for (int gg = 0; gg < 8; gg++) s += ps[gg * 32 + tid];
        float c = ct[tid];
        float sp = log1pf(expf(c));
        z[(size_t)token * 32 + tid] = tanhf(s / (sp + 1e-4f));
    }
}

// ---------------- host ------------------------------------------------------
static float* sym_addr_f(const void* symbol) {
    void* p = nullptr;
    cudaGetSymbolAddress(&p, symbol);
    return (float*)p;
}
static __nv_bfloat16* sym_addr_b(const void* symbol) {
    void* p = nullptr;
    cudaGetSymbolAddress(&p, symbol);
    return (__nv_bfloat16*)p;
}

extern "C" void kernel_launch(void* const* d_in, const int* in_sizes, int n_in,
                              void* d_out, int out_size) {
    const float* x     = (const float*)d_in[0];
    const float* qp    = (const float*)d_in[1];
    const float* kp    = (const float*)d_in[2];
    const float* wv    = (const float*)d_in[3];
    const float* wproj = (const float*)d_in[4];
    const float* qgain = (const float*)d_in[5];
    const float* ew0   = (const float*)d_in[6];
    const float* g1    = (const float*)d_in[7];
    const float* b1    = (const float*)d_in[8];
    const float* ew1   = (const float*)d_in[9];
    const float* g2    = (const float*)d_in[10];
    const float* b2    = (const float*)d_in[11];
    const float* ew2   = (const float*)d_in[12];
    const float* ewout = (const float*)d_in[13];
    const float* ct    = (const float*)d_in[14];
    float* z = (float*)d_out;

    float* wqk   = sym_addr_f(g_wqk);
    float* qkraw = sym_addr_f(g_qkraw);
    float* v     = sym_addr_f(g_v);
    float* h     = sym_addr_f(g_h);
    float* he0   = sym_addr_f(g_he0);
    float* he1   = sym_addr_f(g_he1);
    float* he2   = sym_addr_f(g_he2);
    float* hrms  = sym_addr_f(g_hrms);

    __nv_bfloat16* a16   = sym_addr_b(g_a16);
    __nv_bfloat16* b16   = sym_addr_b(g_b16);
    __nv_bfloat16* wqk16 = sym_addr_b(g_w16qk);
    __nv_bfloat16* wv16  = sym_addr_b(g_w16v);
    __nv_bfloat16* wp16  = sym_addr_b(g_w16p);
    __nv_bfloat16* we016 = sym_addr_b(g_w16e0);
    __nv_bfloat16* we116 = sym_addr_b(g_w16e1);
    __nv_bfloat16* we216 = sym_addr_b(g_w16e2);

    cudaFuncSetAttribute(gemm_mma_kernel,
                         cudaFuncAttributeMaxDynamicSharedMemorySize, GSMEM);

    dim3 ggrid(4, 32);   // N/128 = 4, M/128 = 32 -> 128 CTAs, one wave
    const int WBLK = 512 * 512 / 256;
    const int ABLK = NTOK * 512 / 256;

    // slot 3 (ncu capture point) = gemm_mma_kernel; dependencies respected
    conv_act_kernel<<<ABLK, 256>>>(x, a16);                                       // 0
    conv_w_kernel<<<WBLK, 256>>>(wv, wv16);                                       // 1
    trig_table_kernel<<<256, 128>>>();                                            // 2
    gemm_mma_kernel<<<ggrid, 256, GSMEM>>>(a16, wv16, nullptr, v, nullptr, 0);    // 3 <- profiled
    prep_wqk_kernel<<<512, 256>>>(qp, kp);                                        // 4
    conv_w5_kernel<<<dim3(WBLK, 5), 256>>>(wqk, wproj, ew0, ew1, ew2,             // 5
                                           wqk16, wp16, we016, we116, we216);
    gemm_mma_kernel<<<ggrid, 256, GSMEM>>>(a16, wqk16, nullptr, qkraw, nullptr, 0); // 6
    rope_kernel<<<4096, 256>>>(qkraw, qgain);                                     // 7
    attn_kernel<<<dim3(16, 16), 128>>>(b16);                                      // 8
    gemm_mma_kernel<<<ggrid, 256, GSMEM>>>(b16, wp16, x, h, a16, 1);              // 9
    gemm_mma_kernel<<<ggrid, 256, GSMEM>>>(a16, we016, nullptr, he0, nullptr, 0); // 10
    ln_split_kernel<<<4096, 256>>>(he0, g1, b1, b16);                             // 11
    gemm_mma_kernel<<<ggrid, 256, GSMEM>>>(b16, we116, h, he1, nullptr, 2);       // 12
    ln_split_kernel<<<4096, 256>>>(he1, g2, b2, a16);                             // 13
    gemm_mma_kernel<<<ggrid, 256, GSMEM>>>(a16, we216, he1, he2, nullptr, 2);     // 14
    rms_kernel<<<4096, 256>>>(he2, hrms);                                         // 15
    zout_kernel<<<4096, 256>>>(hrms, ewout, ct, z);                               // 16
}

// round 7
// speedup vs baseline: 2.1633x; 1.5214x over previous
#include <cuda_runtime.h>
#include <cuda_bf16.h>
#include <math.h>
#include <stdint.h>

#define T_SEQ 2048
#define NTOK  4096
#define DM    512
#define NH    8
#define DH    64
#define DP    32

typedef unsigned long long ull;

// ---------------- mma / async helpers ----------------------------------------
__device__ __forceinline__ uint32_t smem_u32(const void* p) {
    uint32_t a;
    asm("{ .reg .u64 t; cvta.to.shared.u64 t, %1; cvt.u32.u64 %0, t; }"
        : "=r"(a) : "l"(p));
    return a;
}
__device__ __forceinline__ void cp16(uint32_t dst, const void* src) {
    asm volatile("cp.async.cg.shared.global [%0], [%1], 16;"
        :: "r"(dst), "l"(src) : "memory");
}
__device__ __forceinline__ void ldsm4(uint32_t& r0, uint32_t& r1, uint32_t& r2,
                                      uint32_t& r3, uint32_t addr) {
    asm volatile("ldmatrix.sync.aligned.m8n8.x4.shared.b16 {%0,%1,%2,%3}, [%4];"
        : "=r"(r0), "=r"(r1), "=r"(r2), "=r"(r3) : "r"(addr));
}
__device__ __forceinline__ void mma16816(float& c0, float& c1, float& c2, float& c3,
                                         uint32_t a0, uint32_t a1, uint32_t a2,
                                         uint32_t a3, uint32_t b0, uint32_t b1) {
    asm volatile("mma.sync.aligned.m16n8k16.row.col.f32.bf16.bf16.f32 "
        "{%0,%1,%2,%3}, {%4,%5,%6,%7}, {%8,%9}, {%0,%1,%2,%3};"
        : "+f"(c0), "+f"(c1), "+f"(c2), "+f"(c3)
        : "r"(a0), "r"(a1), "r"(a2), "r"(a3), "r"(b0), "r"(b1));
}

// ---------------- scratch (device globals) ----------------------------------
__device__ __align__(16) float g_wqk[512 * 512];
__device__ __align__(16) float g_qkraw[NTOK * 512];
__device__ __align__(16) float g_v[NTOK * DM];
__device__ __align__(16) float g_h[NTOK * DM];
__device__ __align__(16) float g_he0[NTOK * DM];
__device__ __align__(16) float g_he1[NTOK * DM];
__device__ __align__(16) float g_he2[NTOK * DM];
__device__ __align__(16) float g_hrms[NTOK * DM];
__device__ __align__(16) float g_cos[T_SEQ * 16];
__device__ __align__(16) float g_sin[T_SEQ * 16];

// q/k bf16 split: [bh][t][96]; q = [qh|ql|qh], k = [kh|kh|kl]
__device__ __align__(16) __nv_bfloat16 g_qs[16 * T_SEQ * 96];
__device__ __align__(16) __nv_bfloat16 g_ks[16 * T_SEQ * 96];
// transposed V splits: [bh][dim 64][t 2048]
__device__ __align__(16) __nv_bfloat16 g_vth[16 * 64 * T_SEQ];
__device__ __align__(16) __nv_bfloat16 g_vtl[16 * 64 * T_SEQ];

// activation split buffers (A/B ping-pong): [4096][1536] = [hi|lo|hi]
__device__ __align__(16) __nv_bfloat16 g_a16[NTOK * 1536];
__device__ __align__(16) __nv_bfloat16 g_b16[NTOK * 1536];
// weight split buffers: [512][1536] = [hi|hi|lo]
__device__ __align__(16) __nv_bfloat16 g_w16qk[512 * 1536];
__device__ __align__(16) __nv_bfloat16 g_w16v[512 * 1536];
__device__ __align__(16) __nv_bfloat16 g_w16p[512 * 1536];
__device__ __align__(16) __nv_bfloat16 g_w16e0[512 * 1536];
__device__ __align__(16) __nv_bfloat16 g_w16e1[512 * 1536];
__device__ __align__(16) __nv_bfloat16 g_w16e2[512 * 1536];

// ---------------- RoPE trig table -------------------------------------------
__global__ void trig_table_kernel() {
    int idx = blockIdx.x * blockDim.x + threadIdx.x;
    if (idx >= T_SEQ * 16) return;
    int t = idx >> 4, i = idx & 15;
    double p = pow(10000.0, (double)i / 16.0);
    float pf = (float)p;
    float freq = 1.0f / pf;
    float ang = (float)t * freq;
    g_cos[idx] = (float)cos((double)ang);
    g_sin[idx] = (float)sin((double)ang);
}

// ---------------- pack q_projs/k_projs [h][d][o] -> W[n][d] -----------------
__global__ void prep_wqk_kernel(const float* __restrict__ qp,
                                const float* __restrict__ kp) {
    int n = blockIdx.x;
    const float* src = (n < 256) ? qp : kp;
    int nn = n & 255;
    int h = nn >> 5, o = nn & 31;
    for (int d = threadIdx.x; d < 512; d += blockDim.x)
        g_wqk[n * 512 + d] = src[h * 16384 + d * 32 + o];
}

// ---------------- batched weight conversion (6 matrices) --------------------
__global__ __launch_bounds__(256) void conv_w6_kernel(
    const float* s0, const float* s1, const float* s2,
    const float* s3, const float* s4, const float* s5,
    __nv_bfloat16* d0, __nv_bfloat16* d1, __nv_bfloat16* d2,
    __nv_bfloat16* d3, __nv_bfloat16* d4, __nv_bfloat16* d5) {
    const float* src; __nv_bfloat16* dst;
    switch (blockIdx.y) {
        case 0: src = s0; dst = d0; break;
        case 1: src = s1; dst = d1; break;
        case 2: src = s2; dst = d2; break;
        case 3: src = s3; dst = d3; break;
        case 4: src = s4; dst = d4; break;
        default: src = s5; dst = d5; break;
    }
    int idx = blockIdx.x * 256 + threadIdx.x;
    int row = idx >> 9, col = idx & 511;
    float x = src[idx];
    __nv_bfloat16 h = __float2bfloat16(x);
    __nv_bfloat16 l = __float2bfloat16(x - __bfloat162float(h));
    size_t base = (size_t)row * 1536;
    dst[base + col] = h;
    dst[base + 512 + col] = h;
    dst[base + 1024 + col] = l;
}

// ---------------- activation conversion (x only) ----------------------------
__global__ __launch_bounds__(256) void conv_act_kernel(const float* __restrict__ in,
                                                       __nv_bfloat16* __restrict__ out) {
    int idx = blockIdx.x * 256 + threadIdx.x;
    int row = idx >> 9, col = idx & 511;
    float x = in[idx];
    __nv_bfloat16 h = __float2bfloat16(x);
    __nv_bfloat16 l = __float2bfloat16(x - __bfloat162float(h));
    size_t base = (size_t)row * 1536;
    out[base + col] = h;
    out[base + 512 + col] = l;
    out[base + 1024 + col] = h;
}

// ---------------- HMMA GEMM (128x128 tile, double-buffered cp.async) --------
#define NKT 24
#define STG 32768
#define GSMEM (2 * STG)
__global__ __launch_bounds__(256) void gemm_mma_kernel(
    const __nv_bfloat16* __restrict__ A16, const __nv_bfloat16* __restrict__ W16,
    const float* __restrict__ R, float* __restrict__ C,
    __nv_bfloat16* __restrict__ S, int epi)
{
    extern __shared__ __align__(128) char sm[];
    uint32_t sb = smem_u32(sm);

    int tid = threadIdx.x, wid = tid >> 5, lane = tid & 31;
    int bm = blockIdx.y * 128, bn = blockIdx.x * 128;
    int wm = wid >> 1, wn = wid & 1;

    const __nv_bfloat16* Abase = A16 + (size_t)bm * 1536;
    const __nv_bfloat16* Wbase = W16 + (size_t)bn * 1536;

    auto load_stage = [&](int kt) {
        uint32_t dA = sb + (uint32_t)(kt & 1) * STG;
        uint32_t dB = dA + 16384;
        int kofs = kt * 64;
#pragma unroll
        for (int it = 0; it < 4; it++) {
            int idx = it * 256 + tid, row = idx >> 3, seg = idx & 7;
            uint32_t off = (uint32_t)(row * 128 + ((seg * 16) ^ ((row & 7) << 4)));
            cp16(dA + off, Abase + (size_t)row * 1536 + kofs + seg * 8);
        }
#pragma unroll
        for (int it = 0; it < 4; it++) {
            int idx = it * 256 + tid, row = idx >> 3, seg = idx & 7;
            uint32_t off = (uint32_t)(row * 128 + ((seg * 16) ^ ((row & 7) << 4)));
            cp16(dB + off, Wbase + (size_t)row * 1536 + kofs + seg * 8);
        }
        asm volatile("cp.async.commit_group;" ::: "memory");
    };

    int aRow[2]; uint32_t aSw[2];
#pragma unroll
    for (int mi = 0; mi < 2; mi++) {
        int row = wm * 32 + mi * 16 + (lane & 15);
        aRow[mi] = row;
        aSw[mi] = (uint32_t)((((lane >> 4) << 4)) ^ ((row & 7) << 4));
    }
    int bRow[4]; uint32_t bSw[4];
#pragma unroll
    for (int g = 0; g < 4; g++) {
        int nrow = wn * 64 + g * 16 + (lane & 7) + ((lane >> 4) << 3);
        bRow[g] = nrow;
        bSw[g] = (uint32_t)(((lane & 8) << 1) ^ ((nrow & 7) << 4));
    }

    float c[2][8][4];
#pragma unroll
    for (int mi = 0; mi < 2; mi++)
#pragma unroll
        for (int ni = 0; ni < 8; ni++)
#pragma unroll
            for (int q = 0; q < 4; q++) c[mi][ni][q] = 0.f;

    load_stage(0);

    for (int kt = 0; kt < NKT; kt++) {
        if (kt + 1 < NKT) {
            load_stage(kt + 1);
            asm volatile("cp.async.wait_group 1;" ::: "memory");
        } else {
            asm volatile("cp.async.wait_group 0;" ::: "memory");
        }
        __syncthreads();
        uint32_t base = sb + (uint32_t)(kt & 1) * STG;
        uint32_t baseB = base + 16384;
#pragma unroll
        for (int ks = 0; ks < 4; ks++) {
            uint32_t a0[4], a1[4], b[4][4];
            ldsm4(a0[0], a0[1], a0[2], a0[3],
                  base + (uint32_t)(aRow[0] * 128) + (uint32_t)((ks * 32) ^ aSw[0]));
            ldsm4(a1[0], a1[1], a1[2], a1[3],
                  base + (uint32_t)(aRow[1] * 128) + (uint32_t)((ks * 32) ^ aSw[1]));
#pragma unroll
            for (int g = 0; g < 4; g++)
                ldsm4(b[g][0], b[g][1], b[g][2], b[g][3],
                      baseB + (uint32_t)(bRow[g] * 128) + (uint32_t)((ks * 32) ^ bSw[g]));
#pragma unroll
            for (int g = 0; g < 4; g++) {
                mma16816(c[0][2 * g][0], c[0][2 * g][1], c[0][2 * g][2], c[0][2 * g][3],
                         a0[0], a0[1], a0[2], a0[3], b[g][0], b[g][1]);
                mma16816(c[0][2 * g + 1][0], c[0][2 * g + 1][1], c[0][2 * g + 1][2], c[0][2 * g + 1][3],
                         a0[0], a0[1], a0[2], a0[3], b[g][2], b[g][3]);
                mma16816(c[1][2 * g][0], c[1][2 * g][1], c[1][2 * g][2], c[1][2 * g][3],
                         a1[0], a1[1], a1[2], a1[3], b[g][0], b[g][1]);
                mma16816(c[1][2 * g + 1][0], c[1][2 * g + 1][1], c[1][2 * g + 1][2], c[1][2 * g + 1][3],
                         a1[0], a1[1], a1[2], a1[3], b[g][2], b[g][3]);
            }
        }
        if (kt + 1 < NKT) __syncthreads();
    }

    int gq = lane >> 2, tig = lane & 3;
#pragma unroll
    for (int mi = 0; mi < 2; mi++) {
#pragma unroll
        for (int ni = 0; ni < 8; ni++) {
#pragma unroll
            for (int half = 0; half < 2; half++) {
                int row = bm + wm * 32 + mi * 16 + gq + half * 8;
                int col = bn + wn * 64 + ni * 8 + tig * 2;
                size_t o = (size_t)row * 512 + col;
                float v0 = c[mi][ni][half * 2], v1 = c[mi][ni][half * 2 + 1];
                if (epi == 1) {
                    float2 rr = *(const float2*)(R + o);
                    v0 += rr.x; v1 += rr.y;
                } else if (epi == 2) {
                    float2 rr = *(const float2*)(R + o);
                    v0 = rr.x + v0 / (1.0f + expf(-v0));
                    v1 = rr.y + v1 / (1.0f + expf(-v1));
                }
                if (C) {
                    float2 ov = {v0, v1};
                    *(float2*)(C + o) = ov;
                }
                if (S) {
                    __nv_bfloat16 h0 = __float2bfloat16(v0);
                    __nv_bfloat16 h1 = __float2bfloat16(v1);
                    __nv_bfloat16 l0 = __float2bfloat16(v0 - __bfloat162float(h0));
                    __nv_bfloat16 l1 = __float2bfloat16(v1 - __bfloat162float(h1));
                    size_t sbase = (size_t)row * 1536 + col;
                    __nv_bfloat162 hh; hh.x = h0; hh.y = h1;
                    __nv_bfloat162 ll; ll.x = l0; ll.y = l1;
                    *(__nv_bfloat162*)(S + sbase) = hh;
                    *(__nv_bfloat162*)(S + sbase + 512) = ll;
                    *(__nv_bfloat162*)(S + sbase + 1024) = hh;
                }
            }
        }
    }
}

// ---------------- RoPE -> bf16 split q/k ------------------------------------
__global__ __launch_bounds__(256) void rope_kernel(const float* __restrict__ qkraw,
                                                   const float* __restrict__ gain) {
    int token = blockIdx.x;
    int b = token >> 11, t = token & 2047;
    int tid = threadIdx.x;
    int h = tid >> 5, o = tid & 31, i = o & 15;
    float c = g_cos[t * 16 + i];
    float s = g_sin[t * 16 + i];
    const float* row = qkraw + (size_t)token * 512;

    float q1 = row[h * 32 + i], q2 = row[h * 32 + i + 16];
    float qv = (o < 16) ? (q1 * c - q2 * s) : (q2 * c + q1 * s);
    qv *= gain[h] * 0.17677669529663687f;

    float k1 = row[256 + h * 32 + i], k2 = row[256 + h * 32 + i + 16];
    float kv = (o < 16) ? (k1 * c - k2 * s) : (k2 * c + k1 * s);

    size_t base = ((size_t)(b * 8 + h) * T_SEQ + t) * 96;
    __nv_bfloat16 qh = __float2bfloat16(qv);
    __nv_bfloat16 ql = __float2bfloat16(qv - __bfloat162float(qh));
    g_qs[base + o] = qh;
    g_qs[base + 32 + o] = ql;
    g_qs[base + 64 + o] = qh;

    __nv_bfloat16 kh = __float2bfloat16(kv);
    __nv_bfloat16 kl = __float2bfloat16(kv - __bfloat162float(kh));
    g_ks[base + o] = kh;
    g_ks[base + 32 + o] = kh;
    g_ks[base + 64 + o] = kl;
}

// ---------------- V transpose + split: g_v -> g_vth/g_vtl -------------------
__global__ __launch_bounds__(256) void vt_kernel() {
    __shared__ float ts[128 * 65];
    int bh = blockIdx.y, b = bh >> 3, h = bh & 7;
    int t0 = blockIdx.x * 128;
    int tid = threadIdx.x;
#pragma unroll
    for (int it = 0; it < 32; it++) {
        int idx = it * 256 + tid;
        int tt = idx >> 6, d = idx & 63;
        ts[tt * 65 + d] = g_v[((size_t)(b * T_SEQ + t0 + tt)) * 512 + h * 64 + d];
    }
    __syncthreads();
    int d = tid >> 2, qd = tid & 3;
    __nv_bfloat16* oh = g_vth + ((size_t)bh * 64 + d) * T_SEQ + t0 + qd * 32;
    __nv_bfloat16* ol = g_vtl + ((size_t)bh * 64 + d) * T_SEQ + t0 + qd * 32;
#pragma unroll
    for (int j2 = 0; j2 < 4; j2++) {
        __nv_bfloat162 hv[4], lv[4];
#pragma unroll
        for (int e2 = 0; e2 < 4; e2++) {
            float x0 = ts[(qd * 32 + j2 * 8 + e2 * 2) * 65 + d];
            float x1 = ts[(qd * 32 + j2 * 8 + e2 * 2 + 1) * 65 + d];
            __nv_bfloat16 h0 = __float2bfloat16(x0);
            __nv_bfloat16 h1 = __float2bfloat16(x1);
            hv[e2].x = h0; hv[e2].y = h1;
            lv[e2].x = __float2bfloat16(x0 - __bfloat162float(h0));
            lv[e2].y = __float2bfloat16(x1 - __bfloat162float(h1));
        }
        *(uint4*)(oh + j2 * 8) = *(uint4*)hv;
        *(uint4*)(ol + j2 * 8) = *(uint4*)lv;
    }
}

// ---------------- MMA flash attention ---------------------------------------
// grid (16 tiles, 16 bh), 256 threads (8 warps x 16 q-rows), 64-key tiles.
#define ATT_SMEM 65536
__global__ __launch_bounds__(256, 1) void attn_mma_kernel(__nv_bfloat16* __restrict__ Y16) {
    extern __shared__ __align__(128) char smA[];
    uint32_t sb = smem_u32(smA);
    const uint32_t smQ = sb, smK = sb + 32768, smVh = sb + 49152, smVl = sb + 57344;

    int tid = threadIdx.x, wid = tid >> 5, lane = tid & 31;
    int gq = lane >> 2, tig = lane & 3;
    int bh = blockIdx.y, b = bh >> 3, h = bh & 7;
    int tileIdx = (int)gridDim.x - 1 - (int)blockIdx.x;
    int tb = tileIdx * 128;

    // load Q once (128 rows x 96 cols, 256B-swizzled rows)
    {
        const __nv_bfloat16* Qg = g_qs + ((size_t)bh * T_SEQ + tb) * 96;
        int row = tid >> 1, sbase = (tid & 1) * 6;
#pragma unroll
        for (int s = 0; s < 6; s++) {
            int seg = sbase + s;
            cp16(smQ + (uint32_t)(row * 256 + ((seg * 16) ^ ((row & 7) << 4))),
                 Qg + (size_t)row * 96 + seg * 8);
        }
        asm volatile("cp.async.commit_group;" ::: "memory");
    }

    float o[8][4];
#pragma unroll
    for (int n = 0; n < 8; n++)
#pragma unroll
        for (int q = 0; q < 4; q++) o[n][q] = 0.f;
    float mLo = -3.0e38f, mHi = -3.0e38f, lLo = 0.f, lHi = 0.f;

    const __nv_bfloat16* Kg = g_ks + (size_t)bh * T_SEQ * 96;
    const __nv_bfloat16* Vhg = g_vth + (size_t)bh * 64 * T_SEQ;
    const __nv_bfloat16* Vlg = g_vtl + (size_t)bh * 64 * T_SEQ;

    // B-frag row patterns (keys / v-dims)
    int nRow[4]; uint32_t nSw[4];
#pragma unroll
    for (int g = 0; g < 4; g++) {
        int nr = g * 16 + (lane & 7) + ((lane >> 4) << 3);
        nRow[g] = nr;
        nSw[g] = (uint32_t)(((lane & 8) << 1));
    }

    int ntk = 2 * (tileIdx + 1);
    int wminr = tb + wid * 16;

    for (int t = 0; t < ntk; t++) {
        int j0 = t * 64;
        {
            int row = tid >> 2;
            int ks = (tid & 3) * 3;
#pragma unroll
            for (int s = 0; s < 3; s++) {
                int seg = ks + s;
                cp16(smK + (uint32_t)(row * 256 + ((seg * 16) ^ ((row & 7) << 4))),
                     Kg + (size_t)(j0 + row) * 96 + seg * 8);
            }
            int vsb = (tid & 3) * 2;
#pragma unroll
            for (int s = 0; s < 2; s++) {
                int seg = vsb + s;
                uint32_t off = (uint32_t)(row * 128 + ((seg * 16) ^ ((row & 7) << 4)));
                cp16(smVh + off, Vhg + (size_t)row * T_SEQ + j0 + seg * 8);
                cp16(smVl + off, Vlg + (size_t)row * T_SEQ + j0 + seg * 8);
            }
            asm volatile("cp.async.commit_group;" ::: "memory");
            asm volatile("cp.async.wait_group 0;" ::: "memory");
        }
        __syncthreads();

        if (j0 <= wminr + 15) {
            // ---- S = Q Kt (k' = 96) ----
            float s[8][4];
#pragma unroll
            for (int n = 0; n < 8; n++)
#pragma unroll
                for (int q = 0; q < 4; q++) s[n][q] = 0.f;

            int qrow = wid * 16 + (lane & 15);
            uint32_t qbase = smQ + (uint32_t)(qrow * 256);
            uint32_t qxor = (uint32_t)((lane >> 4) << 4);
            uint32_t rxor = (uint32_t)((qrow & 7) << 4);
#pragma unroll
            for (int kk = 0; kk < 6; kk++) {
                uint32_t qa[4];
                ldsm4(qa[0], qa[1], qa[2], qa[3],
                      qbase + (uint32_t)(((kk * 32) + qxor) ^ rxor));
#pragma unroll
                for (int g = 0; g < 4; g++) {
                    uint32_t kb[4];
                    uint32_t ka = smK + (uint32_t)(nRow[g] * 256)
                                + (uint32_t)(((kk * 32) + nSw[g]) ^ ((nRow[g] & 7) << 4));
                    ldsm4(kb[0], kb[1], kb[2], kb[3], ka);
                    mma16816(s[2 * g][0], s[2 * g][1], s[2 * g][2], s[2 * g][3],
                             qa[0], qa[1], qa[2], qa[3], kb[0], kb[1]);
                    mma16816(s[2 * g + 1][0], s[2 * g + 1][1], s[2 * g + 1][2], s[2 * g + 1][3],
                             qa[0], qa[1], qa[2], qa[3], kb[2], kb[3]);
                }
            }

            int rowLo = tb + wid * 16 + gq;
            int rowHi = rowLo + 8;
            if (j0 + 63 > wminr) {
#pragma unroll
                for (int n = 0; n < 8; n++) {
                    int k0 = j0 + n * 8 + tig * 2;
                    if (k0 > rowLo)     s[n][0] = -1.0e30f;
                    if (k0 + 1 > rowLo) s[n][1] = -1.0e30f;
                    if (k0 > rowHi)     s[n][2] = -1.0e30f;
                    if (k0 + 1 > rowHi) s[n][3] = -1.0e30f;
                }
            }

            // ---- online softmax ----
            float cLo = -3.0e38f, cHi = -3.0e38f;
#pragma unroll
            for (int n = 0; n < 8; n++) {
                cLo = fmaxf(cLo, fmaxf(s[n][0], s[n][1]));
                cHi = fmaxf(cHi, fmaxf(s[n][2], s[n][3]));
            }
            cLo = fmaxf(cLo, __shfl_xor_sync(0xffffffffu, cLo, 1));
            cLo = fmaxf(cLo, __shfl_xor_sync(0xffffffffu, cLo, 2));
            cHi = fmaxf(cHi, __shfl_xor_sync(0xffffffffu, cHi, 1));
            cHi = fmaxf(cHi, __shfl_xor_sync(0xffffffffu, cHi, 2));
            float mnLo = fmaxf(mLo, cLo), mnHi = fmaxf(mHi, cHi);
            float corrLo = __expf(mLo - mnLo), corrHi = __expf(mHi - mnHi);
            mLo = mnLo; mHi = mnHi;
            lLo *= corrLo; lHi *= corrHi;
#pragma unroll
            for (int n = 0; n < 8; n++) {
                o[n][0] *= corrLo; o[n][1] *= corrLo;
                o[n][2] *= corrHi; o[n][3] *= corrHi;
            }

            uint32_t ph[8][2], pl[8][2];
            float psLo = 0.f, psHi = 0.f;
#pragma unroll
            for (int n = 0; n < 8; n++) {
                float p0 = __expf(s[n][0] - mLo), p1 = __expf(s[n][1] - mLo);
                float p2 = __expf(s[n][2] - mHi), p3 = __expf(s[n][3] - mHi);
                psLo += p0 + p1; psHi += p2 + p3;
                __nv_bfloat162 h01 = __floats2bfloat162_rn(p0, p1);
                __nv_bfloat162 h23 = __floats2bfloat162_rn(p2, p3);
                __nv_bfloat162 l01 = __floats2bfloat162_rn(p0 - __bfloat162float(h01.x),
                                                           p1 - __bfloat162float(h01.y));
                __nv_bfloat162 l23 = __floats2bfloat162_rn(p2 - __bfloat162float(h23.x),
                                                           p3 - __bfloat162float(h23.y));
                ph[n][0] = *(uint32_t*)&h01; ph[n][1] = *(uint32_t*)&h23;
                pl[n][0] = *(uint32_t*)&l01; pl[n][1] = *(uint32_t*)&l23;
            }
            lLo += psLo; lHi += psHi;

            // ---- O += P V : PhVh + PlVh + PhVl ----
#pragma unroll
            for (int kk = 0; kk < 4; kk++) {
#pragma unroll
                for (int g = 0; g < 4; g++) {
                    uint32_t vb[4];
                    uint32_t va = smVh + (uint32_t)(nRow[g] * 128)
                                + (uint32_t)(((kk * 32) + nSw[g]) ^ ((nRow[g] & 7) << 4));
                    ldsm4(vb[0], vb[1], vb[2], vb[3], va);
                    mma16816(o[2 * g][0], o[2 * g][1], o[2 * g][2], o[2 * g][3],
                             ph[2 * kk][0], ph[2 * kk][1], ph[2 * kk + 1][0], ph[2 * kk + 1][1],
                             vb[0], vb[1]);
                    mma16816(o[2 * g + 1][0], o[2 * g + 1][1], o[2 * g + 1][2], o[2 * g + 1][3],
                             ph[2 * kk][0], ph[2 * kk][1], ph[2 * kk + 1][0], ph[2 * kk + 1][1],
                             vb[2], vb[3]);
                    mma16816(o[2 * g][0], o[2 * g][1], o[2 * g][2], o[2 * g][3],
                             pl[2 * kk][0], pl[2 * kk][1], pl[2 * kk + 1][0], pl[2 * kk + 1][1],
                             vb[0], vb[1]);
                    mma16816(o[2 * g + 1][0], o[2 * g + 1][1], o[2 * g + 1][2], o[2 * g + 1][3],
                             pl[2 * kk][0], pl[2 * kk][1], pl[2 * kk + 1][0], pl[2 * kk + 1][1],
                             vb[2], vb[3]);
                }
            }
#pragma unroll
            for (int kk = 0; kk < 4; kk++) {
#pragma unroll
                for (int g = 0; g < 4; g++) {
                    uint32_t vb[4];
                    uint32_t va = smVl + (uint32_t)(nRow[g] * 128)
                                + (uint32_t)(((kk * 32) + nSw[g]) ^ ((nRow[g] & 7) << 4));
                    ldsm4(vb[0], vb[1], vb[2], vb[3], va);
                    mma16816(o[2 * g][0], o[2 * g][1], o[2 * g][2], o[2 * g][3],
                             ph[2 * kk][0], ph[2 * kk][1], ph[2 * kk + 1][0], ph[2 * kk + 1][1],
                             vb[0], vb[1]);
                    mma16816(o[2 * g + 1][0], o[2 * g + 1][1], o[2 * g + 1][2], o[2 * g + 1][3],
                             ph[2 * kk][0], ph[2 * kk][1], ph[2 * kk + 1][0], ph[2 * kk + 1][1],
                             vb[2], vb[3]);
                }
            }
        }
        __syncthreads();
    }

    // ---- epilogue: normalize, self-align removal, split-bf16 write ----
    lLo += __shfl_xor_sync(0xffffffffu, lLo, 1);
    lLo += __shfl_xor_sync(0xffffffffu, lLo, 2);
    lHi += __shfl_xor_sync(0xffffffffu, lHi, 1);
    lHi += __shfl_xor_sync(0xffffffffu, lHi, 2);

#pragma unroll
    for (int hq = 0; hq < 2; hq++) {
        int row = tb + wid * 16 + gq + hq * 8;
        float linv = 1.0f / (hq ? lHi : lLo);
        int tok = b * T_SEQ + row;
        const float* vr = g_v + (size_t)tok * 512 + h * 64;
        float y0[8], y1[8];
        float2 vv[8];
        float n2 = 0.f, pr = 0.f;
#pragma unroll
        for (int n = 0; n < 8; n++) {
            vv[n] = *(const float2*)(vr + n * 8 + tig * 2);
            y0[n] = o[n][hq * 2] * linv;
            y1[n] = o[n][hq * 2 + 1] * linv;
            n2 += vv[n].x * vv[n].x + vv[n].y * vv[n].y;
            pr += y0[n] * vv[n].x + y1[n] * vv[n].y;
        }
        n2 += __shfl_xor_sync(0xffffffffu, n2, 1);
        n2 += __shfl_xor_sync(0xffffffffu, n2, 2);
        pr += __shfl_xor_sync(0xffffffffu, pr, 1);
        pr += __shfl_xor_sync(0xffffffffu, pr, 2);
        float rn = 1.0f / fmaxf(sqrtf(n2), 1e-12f);
        float prn = pr * rn * rn;
        size_t obase = (size_t)tok * 1536 + h * 64;
#pragma unroll
        for (int n = 0; n < 8; n++) {
            float a0 = y0[n] - prn * vv[n].x;
            float a1 = y1[n] - prn * vv[n].y;
            __nv_bfloat16 h0 = __float2bfloat16(a0);
            __nv_bfloat16 h1 = __float2bfloat16(a1);
            __nv_bfloat162 hh; hh.x = h0; hh.y = h1;
            __nv_bfloat162 ll;
            ll.x = __float2bfloat16(a0 - __bfloat162float(h0));
            ll.y = __float2bfloat16(a1 - __bfloat162float(h1));
            size_t p = obase + n * 8 + tig * 2;
            *(__nv_bfloat162*)(Y16 + p) = hh;
            *(__nv_bfloat162*)(Y16 + p + 512) = ll;
            *(__nv_bfloat162*)(Y16 + p + 1024) = hh;
        }
    }
}

// ---------------- layernorm with split-bf16 output --------------------------
__global__ __launch_bounds__(256) void ln_split_kernel(const float* __restrict__ in,
                                                       const float* __restrict__ g,
                                                       const float* __restrict__ b,
                                                       __nv_bfloat16* __restrict__ S) {
    int row = blockIdx.x, tid = threadIdx.x;
    const float* rp = in + (size_t)row * 512;
    float a0 = rp[tid], a1 = rp[tid + 256];
    float s = a0 + a1, s2 = a0 * a0 + a1 * a1;
#pragma unroll
    for (int off = 16; off; off >>= 1) {
        s  += __shfl_down_sync(0xffffffffu, s, off);
        s2 += __shfl_down_sync(0xffffffffu, s2, off);
    }
    __shared__ float rs[8], rs2[8];
    __shared__ float mean_s, inv_s;
    if ((tid & 31) == 0) { rs[tid >> 5] = s; rs2[tid >> 5] = s2; }
    __syncthreads();
    if (tid == 0) {
        float S0 = 0, S2 = 0;
#pragma unroll
        for (int w = 0; w < 8; w++) { S0 += rs[w]; S2 += rs2[w]; }
        float m = S0 * (1.0f / 512.0f);
        float var = fmaxf(S2 * (1.0f / 512.0f) - m * m, 0.0f);
        mean_s = m;
        inv_s = rsqrtf(var + 1e-5f);
    }
    __syncthreads();
    float v0 = (a0 - mean_s) * inv_s * g[tid] + b[tid];
    float v1 = (a1 - mean_s) * inv_s * g[tid + 256] + b[tid + 256];
    size_t base = (size_t)row * 1536;
    __nv_bfloat16 h0 = __float2bfloat16(v0);
    __nv_bfloat16 l0 = __float2bfloat16(v0 - __bfloat162float(h0));
    __nv_bfloat16 h1 = __float2bfloat16(v1);
    __nv_bfloat16 l1 = __float2bfloat16(v1 - __bfloat162float(h1));
    S[base + tid] = h0;       S[base + 512 + tid] = l0;       S[base + 1024 + tid] = h0;
    S[base + tid + 256] = h1; S[base + 512 + tid + 256] = l1; S[base + 1024 + tid + 256] = h1;
}

// ---------------- rms norm --------------------------------------------------
__global__ __launch_bounds__(256) void rms_kernel(const float* __restrict__ in,
                                                  float* __restrict__ out) {
    int row = blockIdx.x, tid = threadIdx.x;
    const float* rp = in + (size_t)row * 512;
    float a0 = rp[tid], a1 = rp[tid + 256];
    float s2 = a0 * a0 + a1 * a1;
#pragma unroll
    for (int off = 16; off; off >>= 1) s2 += __shfl_down_sync(0xffffffffu, s2, off);
    __shared__ float rs2[8];
    __shared__ float inv_s;
    if ((tid & 31) == 0) rs2[tid >> 5] = s2;
    __syncthreads();
    if (tid == 0) {
        float S2 = 0;
#pragma unroll
        for (int w = 0; w < 8; w++) S2 += rs2[w];
        inv_s = rsqrtf(S2 * (1.0f / 512.0f) + 1e-6f);
    }
    __syncthreads();
    out[(size_t)row * 512 + tid]       = a0 * inv_s;
    out[(size_t)row * 512 + tid + 256] = a1 * inv_s;
}

// ---------------- final projection + tanh(coord temp) -----------------------
__global__ __launch_bounds__(256) void zout_kernel(const float* __restrict__ hrms,
                                                   const float* __restrict__ wout,
                                                   const float* __restrict__ ct,
                                                   float* __restrict__ z) {
    int token = blockIdx.x, tid = threadIdx.x;
    __shared__ float xs[512];
    __shared__ float ps[256];
    const float* rp = hrms + (size_t)token * 512;
    xs[tid] = rp[tid];
    xs[tid + 256] = rp[tid + 256];
    __syncthreads();
    int n = tid & 31, g = tid >> 5;
    const float* wr = wout + n * 512 + g * 64;
    const float* xr = xs + g * 64;
    float p = 0.f;
#pragma unroll
    for (int d = 0; d < 64; d++) p += xr[d] * wr[d];
    ps[tid] = p;
    __syncthreads();
    if (tid < 32) {
        float s = 0.f;
#pragma unroll
        for (int gg = 0; gg < 8; gg++) s += ps[gg * 32 + tid];
        float c = ct[tid];
        float sp = log1pf(expf(c));
        z[(size_t)token * 32 + tid] = tanhf(s / (sp + 1e-4f));
    }
}

// ---------------- host ------------------------------------------------------
static float* sym_addr_f(const void* symbol) {
    void* p = nullptr;
    cudaGetSymbolAddress(&p, symbol);
    return (float*)p;
}
static __nv_bfloat16* sym_addr_b(const void* symbol) {
    void* p = nullptr;
    cudaGetSymbolAddress(&p, symbol);
    return (__nv_bfloat16*)p;
}

extern "C" void kernel_launch(void* const* d_in, const int* in_sizes, int n_in,
                              void* d_out, int out_size) {
    const float* x     = (const float*)d_in[0];
    const float* qp    = (const float*)d_in[1];
    const float* kp    = (const float*)d_in[2];
    const float* wv    = (const float*)d_in[3];
    const float* wproj = (const float*)d_in[4];
    const float* qgain = (const float*)d_in[5];
    const float* ew0   = (const float*)d_in[6];
    const float* g1    = (const float*)d_in[7];
    const float* b1    = (const float*)d_in[8];
    const float* ew1   = (const float*)d_in[9];
    const float* g2    = (const float*)d_in[10];
    const float* b2    = (const float*)d_in[11];
    const float* ew2   = (const float*)d_in[12];
    const float* ewout = (const float*)d_in[13];
    const float* ct    = (const float*)d_in[14];
    float* z = (float*)d_out;

    float* wqk   = sym_addr_f(g_wqk);
    float* qkraw = sym_addr_f(g_qkraw);
    float* v     = sym_addr_f(g_v);
    float* h     = sym_addr_f(g_h);
    float* he0   = sym_addr_f(g_he0);
    float* he1   = sym_addr_f(g_he1);
    float* he2   = sym_addr_f(g_he2);
    float* hrms  = sym_addr_f(g_hrms);

    __nv_bfloat16* a16   = sym_addr_b(g_a16);
    __nv_bfloat16* b16   = sym_addr_b(g_b16);
    __nv_bfloat16* wqk16 = sym_addr_b(g_w16qk);
    __nv_bfloat16* wv16  = sym_addr_b(g_w16v);
    __nv_bfloat16* wp16  = sym_addr_b(g_w16p);
    __nv_bfloat16* we016 = sym_addr_b(g_w16e0);
    __nv_bfloat16* we116 = sym_addr_b(g_w16e1);
    __nv_bfloat16* we216 = sym_addr_b(g_w16e2);

    cudaFuncSetAttribute(gemm_mma_kernel,
                         cudaFuncAttributeMaxDynamicSharedMemorySize, GSMEM);
    cudaFuncSetAttribute(attn_mma_kernel,
                         cudaFuncAttributeMaxDynamicSharedMemorySize, ATT_SMEM);

    dim3 ggrid(4, 32);
    const int WBLK = 512 * 512 / 256;
    const int ABLK = NTOK * 512 / 256;

    prep_wqk_kernel<<<512, 256>>>(qp, kp);                                        // 0
    conv_act_kernel<<<ABLK, 256>>>(x, a16);                                       // 1
    conv_w6_kernel<<<dim3(WBLK, 6), 256>>>(wqk, wv, wproj, ew0, ew1, ew2,         // 2
                                           wqk16, wv16, wp16, we016, we116, we216);
    gemm_mma_kernel<<<ggrid, 256, GSMEM>>>(a16, wqk16, nullptr, qkraw, nullptr, 0); // 3 <- profiled
    gemm_mma_kernel<<<ggrid, 256, GSMEM>>>(a16, wv16, nullptr, v, nullptr, 0);    // 4
    trig_table_kernel<<<256, 128>>>();                                            // 5
    rope_kernel<<<4096, 256>>>(qkraw, qgain);                                     // 6
    vt_kernel<<<dim3(16, 16), 256>>>();                                           // 7
    attn_mma_kernel<<<dim3(16, 16), 256, ATT_SMEM>>>(b16);                        // 8
    gemm_mma_kernel<<<ggrid, 256, GSMEM>>>(b16, wp16, x, h, a16, 1);              // 9
    gemm_mma_kernel<<<ggrid, 256, GSMEM>>>(a16, we016, nullptr, he0, nullptr, 0); // 10
    ln_split_kernel<<<4096, 256>>>(he0, g1, b1, b16);                             // 11
    gemm_mma_kernel<<<ggrid, 256, GSMEM>>>(b16, we116, h, he1, nullptr, 2);       // 12
    ln_split_kernel<<<4096, 256>>>(he1, g2, b2, a16);                             // 13
    gemm_mma_kernel<<<ggrid, 256, GSMEM>>>(a16, we216, he1, he2, nullptr, 2);     // 14
    rms_kernel<<<4096, 256>>>(he2, hrms);                                         // 15
    zout_kernel<<<4096, 256>>>(hrms, ewout, ct, z);                               // 16
}